// round 2
// baseline (speedup 1.0000x reference)
#include <cuda_runtime.h>
#include <cuda_bf16.h>

#define Nn      50000
#define Ee      800000
#define IN_DIM  512
#define HIDD    256
#define OUTD    64

// ---------------- scratch (device globals; no allocs allowed) ----------------
__device__ float g_H1[(size_t)Nn * HIDD];   // x @ W1
__device__ float g_S1[(size_t)Nn * HIDD];   // relu(spmm(H1)+b1)
__device__ float g_H2[(size_t)Nn * OUTD];   // S1 @ W2
__device__ int   g_cnt[Nn];                 // histogram, then scatter fill cursor
__device__ int   g_rowptr[Nn + 1];
__device__ int   g_ecol[Ee];
__device__ float g_eval[Ee];

// ---------------- CSR build ----------------
__global__ void k_zero_cnt() {
    int i = blockIdx.x * blockDim.x + threadIdx.x;
    if (i < Nn) g_cnt[i] = 0;
}

__global__ void k_hist(const int* __restrict__ rows) {
    int e = blockIdx.x * blockDim.x + threadIdx.x;
    if (e < Ee) atomicAdd(&g_cnt[rows[e]], 1);
}

__global__ void k_scan() {
    const int T = 1024;
    const int ITEMS = (Nn + T - 1) / T;
    __shared__ int sA[T], sB[T];
    int tid = threadIdx.x;
    int base = tid * ITEMS;

    int sum = 0;
    for (int i = 0; i < ITEMS; i++) {
        int idx = base + i;
        if (idx < Nn) sum += g_cnt[idx];
    }
    sA[tid] = sum;
    __syncthreads();

    int* in = sA; int* out = sB;
    for (int off = 1; off < T; off <<= 1) {
        out[tid] = in[tid] + (tid >= off ? in[tid - off] : 0);
        __syncthreads();
        int* t = in; in = out; out = t;
    }
    int run = (tid == 0) ? 0 : in[tid - 1];
    for (int i = 0; i < ITEMS; i++) {
        int idx = base + i;
        if (idx < Nn) {
            g_rowptr[idx] = run;
            run += g_cnt[idx];
            g_cnt[idx] = 0;
        }
    }
    if (tid == T - 1) g_rowptr[Nn] = Ee;
}

__global__ void k_scatter(const int* __restrict__ rows,
                          const int* __restrict__ cols,
                          const float* __restrict__ vals) {
    int e = blockIdx.x * blockDim.x + threadIdx.x;
    if (e >= Ee) return;
    int r = rows[e];
    int pos = g_rowptr[r] + atomicAdd(&g_cnt[r], 1);
    g_ecol[pos] = cols[e];
    g_eval[pos] = vals[e];
}

// ---------------- TF32 split helpers ----------------
__device__ __forceinline__ unsigned f2tf(float x) {
    unsigned r;
    asm("cvt.rna.tf32.f32 %0, %1;" : "=r"(r) : "f"(x));
    return r;
}

// returns (hi, lo) as float bit patterns of tf32 values
__device__ __forceinline__ float2 tf_split(float x) {
    unsigned hu = f2tf(x);
    float hf = __uint_as_float(hu);
    float lo = x - hf;                 // exact
    unsigned lu = f2tf(lo);
    return make_float2(__uint_as_float(hu), __uint_as_float(lu));
}

__device__ __forceinline__ void mma_tf32(float* d, const unsigned* a, const unsigned* b) {
    asm volatile(
        "mma.sync.aligned.m16n8k8.row.col.f32.tf32.tf32.f32 "
        "{%0,%1,%2,%3}, {%4,%5,%6,%7}, {%8,%9}, {%0,%1,%2,%3};\n"
        : "+f"(d[0]), "+f"(d[1]), "+f"(d[2]), "+f"(d[3])
        : "r"(a[0]), "r"(a[1]), "r"(a[2]), "r"(a[3]), "r"(b[0]), "r"(b[1]));
}

// ---------------- split-TF32 tensor-core GEMM ----------------
// C[M,Nd] = A[M,K] @ B[K,Nd], fp32 in/out, ~fp32 accuracy (3xTF32).
// Block tile: 128 x BN, BK=32, 256 threads (8 warps: 2 in M x 4 in N).
// Warp tile: 64 x (BN/4). SMEM keeps interleaved (hi,lo) float2 planes.
template <int BN>
__device__ __forceinline__ void mma_gemm_body(const float* __restrict__ A,
                                              const float* __restrict__ B,
                                              float* __restrict__ C,
                                              int M, int K, int Nd) {
    constexpr int BK = 32;
    constexpr int APAD = 33;          // A row stride in float2
    constexpr int BPAD = BN + 2;      // B row stride in float2
    constexpr int NT = BN / 32;       // n8 tiles per warp

    extern __shared__ float2 sm[];
    float2 (*As)[APAD] = (float2(*)[APAD])sm;             // [m][k]
    float2 (*Bs)[BPAD] = (float2(*)[BPAD])(sm + 128 * APAD);  // [k][n]

    const int tid = threadIdx.x;
    const int lane = tid & 31;
    const int warp = tid >> 5;
    const int wm = warp >> 2;          // 0..1
    const int wn = warp & 3;           // 0..3
    const int g = lane >> 2;           // 0..7
    const int t4 = lane & 3;           // 0..3
    const int rowBase = blockIdx.x * 128;
    const int colBase = blockIdx.y * BN;

    float acc[4][NT][4];
#pragma unroll
    for (int mt = 0; mt < 4; mt++)
#pragma unroll
        for (int nt = 0; nt < NT; nt++)
#pragma unroll
            for (int i = 0; i < 4; i++) acc[mt][nt][i] = 0.0f;

    // A load mapping: 128 rows x 32 cols, 4 passes of 32 rows
    const int ar = tid >> 3;           // 0..31
    const int ac = (tid & 7) * 4;      // 0..28
    // B load mapping
    constexpr int TPR = BN / 4;            // threads per B row
    constexpr int BROWS = 256 / TPR;       // rows per pass
    constexpr int BPASS = BK / BROWS;      // passes
    const int bkr = tid / TPR;
    const int bnc = (tid % TPR) * 4;

    for (int k0 = 0; k0 < K; k0 += BK) {
        // ---- load + split A tile ----
#pragma unroll
        for (int p = 0; p < 4; p++) {
            int m = ar + p * 32;
            int gr = rowBase + m;
            float4 v = make_float4(0.f, 0.f, 0.f, 0.f);
            if (gr < M) v = *(const float4*)&A[(size_t)gr * K + k0 + ac];
            As[m][ac + 0] = tf_split(v.x);
            As[m][ac + 1] = tf_split(v.y);
            As[m][ac + 2] = tf_split(v.z);
            As[m][ac + 3] = tf_split(v.w);
        }
        // ---- load + split B tile ----
#pragma unroll
        for (int p = 0; p < BPASS; p++) {
            int k = bkr + p * BROWS;
            float4 v = *(const float4*)&B[(size_t)(k0 + k) * Nd + colBase + bnc];
            Bs[k][bnc + 0] = tf_split(v.x);
            Bs[k][bnc + 1] = tf_split(v.y);
            Bs[k][bnc + 2] = tf_split(v.z);
            Bs[k][bnc + 3] = tf_split(v.w);
        }
        __syncthreads();

#pragma unroll
        for (int ks = 0; ks < BK / 8; ks++) {
            const int kk = ks * 8;
            unsigned ah[4][4], al[4][4];
#pragma unroll
            for (int mt = 0; mt < 4; mt++) {
                int r0 = wm * 64 + mt * 16 + g;
                float2 p0 = As[r0][kk + t4];
                float2 p1 = As[r0 + 8][kk + t4];
                float2 p2 = As[r0][kk + t4 + 4];
                float2 p3 = As[r0 + 8][kk + t4 + 4];
                ah[mt][0] = __float_as_uint(p0.x); al[mt][0] = __float_as_uint(p0.y);
                ah[mt][1] = __float_as_uint(p1.x); al[mt][1] = __float_as_uint(p1.y);
                ah[mt][2] = __float_as_uint(p2.x); al[mt][2] = __float_as_uint(p2.y);
                ah[mt][3] = __float_as_uint(p3.x); al[mt][3] = __float_as_uint(p3.y);
            }
            unsigned bh[NT][2], bl[NT][2];
#pragma unroll
            for (int nt = 0; nt < NT; nt++) {
                int cn = wn * (BN / 4) + nt * 8 + g;
                float2 q0 = Bs[kk + t4][cn];
                float2 q1 = Bs[kk + t4 + 4][cn];
                bh[nt][0] = __float_as_uint(q0.x); bl[nt][0] = __float_as_uint(q0.y);
                bh[nt][1] = __float_as_uint(q1.x); bl[nt][1] = __float_as_uint(q1.y);
            }
#pragma unroll
            for (int mt = 0; mt < 4; mt++)
#pragma unroll
                for (int nt = 0; nt < NT; nt++) {
                    mma_tf32(acc[mt][nt], ah[mt], bh[nt]);  // hi*hi
                    mma_tf32(acc[mt][nt], ah[mt], bl[nt]);  // hi*lo
                    mma_tf32(acc[mt][nt], al[mt], bh[nt]);  // lo*hi
                }
        }
        __syncthreads();
    }

    // ---- epilogue ----
#pragma unroll
    for (int mt = 0; mt < 4; mt++) {
        int r0 = rowBase + wm * 64 + mt * 16 + g;
#pragma unroll
        for (int nt = 0; nt < NT; nt++) {
            int cn = colBase + wn * (BN / 4) + nt * 8 + t4 * 2;
            if (r0 < M)
                *(float2*)&C[(size_t)r0 * Nd + cn] =
                    make_float2(acc[mt][nt][0], acc[mt][nt][1]);
            if (r0 + 8 < M)
                *(float2*)&C[(size_t)(r0 + 8) * Nd + cn] =
                    make_float2(acc[mt][nt][2], acc[mt][nt][3]);
        }
    }
}

__global__ __launch_bounds__(256) void k_gemm1(const float* __restrict__ x,
                                               const float* __restrict__ W1) {
    mma_gemm_body<128>(x, W1, g_H1, Nn, IN_DIM, HIDD);
}

__global__ __launch_bounds__(256) void k_gemm2(const float* __restrict__ W2) {
    mma_gemm_body<64>(g_S1, W2, g_H2, Nn, HIDD, OUTD);
}

// ---------------- SpMM 1: S1 = relu(csr_spmm(H1) + b1), one block per row ----------------
__global__ __launch_bounds__(HIDD) void k_spmm1(const float* __restrict__ b1) {
    int row = blockIdx.x;
    int d = threadIdx.x;
    int s = g_rowptr[row];
    int e = g_rowptr[row + 1];
    float acc = 0.0f;
    int j = s;
    for (; j + 4 <= e; j += 4) {
        int   c0 = g_ecol[j + 0], c1 = g_ecol[j + 1], c2 = g_ecol[j + 2], c3 = g_ecol[j + 3];
        float v0 = g_eval[j + 0], v1 = g_eval[j + 1], v2 = g_eval[j + 2], v3 = g_eval[j + 3];
        float h0 = g_H1[(size_t)c0 * HIDD + d];
        float h1 = g_H1[(size_t)c1 * HIDD + d];
        float h2 = g_H1[(size_t)c2 * HIDD + d];
        float h3 = g_H1[(size_t)c3 * HIDD + d];
        acc = fmaf(v0, h0, acc);
        acc = fmaf(v1, h1, acc);
        acc = fmaf(v2, h2, acc);
        acc = fmaf(v3, h3, acc);
    }
    for (; j < e; j++) {
        acc = fmaf(g_eval[j], g_H1[(size_t)g_ecol[j] * HIDD + d], acc);
    }
    acc += b1[d];
    g_S1[(size_t)row * HIDD + d] = fmaxf(acc, 0.0f);
}

// ---------------- SpMM 2: out = csr_spmm(H2) + b2 ----------------
__global__ __launch_bounds__(256) void k_spmm2(const float* __restrict__ b2,
                                               float* __restrict__ out) {
    int row = blockIdx.x * 4 + (threadIdx.x >> 6);
    int d = threadIdx.x & 63;
    if (row >= Nn) return;
    int s = g_rowptr[row];
    int e = g_rowptr[row + 1];
    float acc = 0.0f;
    int j = s;
    for (; j + 4 <= e; j += 4) {
        int   c0 = g_ecol[j + 0], c1 = g_ecol[j + 1], c2 = g_ecol[j + 2], c3 = g_ecol[j + 3];
        float v0 = g_eval[j + 0], v1 = g_eval[j + 1], v2 = g_eval[j + 2], v3 = g_eval[j + 3];
        acc = fmaf(v0, g_H2[(size_t)c0 * OUTD + d], acc);
        acc = fmaf(v1, g_H2[(size_t)c1 * OUTD + d], acc);
        acc = fmaf(v2, g_H2[(size_t)c2 * OUTD + d], acc);
        acc = fmaf(v3, g_H2[(size_t)c3 * OUTD + d], acc);
    }
    for (; j < e; j++) {
        acc = fmaf(g_eval[j], g_H2[(size_t)g_ecol[j] * OUTD + d], acc);
    }
    out[(size_t)row * OUTD + d] = acc + b2[d];
}

// ---------------- entry point ----------------
extern "C" void kernel_launch(void* const* d_in, const int* in_sizes, int n_in,
                              void* d_out, int out_size) {
    const float* x    = (const float*)d_in[0];
    const int*   rows = (const int*)  d_in[1];
    const int*   cols = (const int*)  d_in[2];
    const float* vals = (const float*)d_in[3];
    const float* W1   = (const float*)d_in[4];
    const float* b1   = (const float*)d_in[5];
    const float* W2   = (const float*)d_in[6];
    const float* b2   = (const float*)d_in[7];
    float* out = (float*)d_out;

    const int smem1 = (128 * 33 + 32 * (128 + 2)) * (int)sizeof(float2);  // 67072
    const int smem2 = (128 * 33 + 32 * (64 + 2)) * (int)sizeof(float2);   // 50688
    cudaFuncSetAttribute(k_gemm1, cudaFuncAttributeMaxDynamicSharedMemorySize, smem1);
    cudaFuncSetAttribute(k_gemm2, cudaFuncAttributeMaxDynamicSharedMemorySize, smem2);

    // CSR build
    k_zero_cnt<<<(Nn + 255) / 256, 256>>>();
    k_hist<<<(Ee + 255) / 256, 256>>>(rows);
    k_scan<<<1, 1024>>>();
    k_scatter<<<(Ee + 255) / 256, 256>>>(rows, cols, vals);

    // layer 1
    k_gemm1<<<dim3((Nn + 127) / 128, HIDD / 128), 256, smem1>>>(x, W1);
    k_spmm1<<<Nn, HIDD>>>(b1);

    // layer 2
    k_gemm2<<<dim3((Nn + 127) / 128, 1), 256, smem2>>>(W2);
    k_spmm2<<<(Nn + 3) / 4, 256>>>(b2, out);
}

// round 3
// speedup vs baseline: 1.5650x; 1.5650x over previous
#include <cuda_runtime.h>
#include <cuda_bf16.h>

#define Nn      50000
#define Ee      800000
#define IN_DIM  512
#define HIDD    256
#define OUTD    64

// ---------------- scratch (device globals; no allocs allowed) ----------------
__device__ float g_H1[(size_t)Nn * HIDD];   // x @ W1
__device__ float g_S1[(size_t)Nn * HIDD];   // relu(spmm(H1)+b1)
__device__ float g_H2[(size_t)Nn * OUTD];   // S1 @ W2
__device__ int   g_cnt[Nn];
__device__ int   g_rowptr[Nn + 1];
__device__ int   g_ecol[Ee];
__device__ float g_eval[Ee];

// ---------------- CSR build ----------------
__global__ void k_zero_cnt() {
    int i = blockIdx.x * blockDim.x + threadIdx.x;
    if (i < Nn) g_cnt[i] = 0;
}

__global__ void k_hist(const int* __restrict__ rows) {
    int e = blockIdx.x * blockDim.x + threadIdx.x;
    if (e < Ee) atomicAdd(&g_cnt[rows[e]], 1);
}

__global__ void k_scan() {
    const int T = 1024;
    const int ITEMS = (Nn + T - 1) / T;
    __shared__ int sA[T], sB[T];
    int tid = threadIdx.x;
    int base = tid * ITEMS;

    int sum = 0;
    for (int i = 0; i < ITEMS; i++) {
        int idx = base + i;
        if (idx < Nn) sum += g_cnt[idx];
    }
    sA[tid] = sum;
    __syncthreads();

    int* in = sA; int* out = sB;
    for (int off = 1; off < T; off <<= 1) {
        out[tid] = in[tid] + (tid >= off ? in[tid - off] : 0);
        __syncthreads();
        int* t = in; in = out; out = t;
    }
    int run = (tid == 0) ? 0 : in[tid - 1];
    for (int i = 0; i < ITEMS; i++) {
        int idx = base + i;
        if (idx < Nn) {
            g_rowptr[idx] = run;
            run += g_cnt[idx];
            g_cnt[idx] = 0;
        }
    }
    if (tid == T - 1) g_rowptr[Nn] = Ee;
}

__global__ void k_scatter(const int* __restrict__ rows,
                          const int* __restrict__ cols,
                          const float* __restrict__ vals) {
    int e = blockIdx.x * blockDim.x + threadIdx.x;
    if (e >= Ee) return;
    int r = rows[e];
    int pos = g_rowptr[r] + atomicAdd(&g_cnt[r], 1);
    g_ecol[pos] = cols[e];
    g_eval[pos] = vals[e];
}

// ---------------- bf16 split helpers ----------------
__device__ __forceinline__ void bf_split(float x, unsigned short& h, unsigned short& l) {
    __nv_bfloat16 hb = __float2bfloat16_rn(x);
    float r = x - __bfloat162float(hb);
    __nv_bfloat16 lb = __float2bfloat16_rn(r);
    h = __bfloat16_as_ushort(hb);
    l = __bfloat16_as_ushort(lb);
}

__device__ __forceinline__ unsigned pack2(unsigned short a, unsigned short b) {
    return (unsigned)a | ((unsigned)b << 16);
}

__device__ __forceinline__ unsigned smem_u32(const void* p) {
    return (unsigned)__cvta_generic_to_shared(p);
}

__device__ __forceinline__ void ldsm_x4(unsigned* r, unsigned addr) {
    asm volatile("ldmatrix.sync.aligned.m8n8.x4.shared.b16 {%0,%1,%2,%3}, [%4];"
                 : "=r"(r[0]), "=r"(r[1]), "=r"(r[2]), "=r"(r[3]) : "r"(addr));
}

__device__ __forceinline__ void ldsm_x4_t(unsigned* r, unsigned addr) {
    asm volatile("ldmatrix.sync.aligned.m8n8.x4.trans.shared.b16 {%0,%1,%2,%3}, [%4];"
                 : "=r"(r[0]), "=r"(r[1]), "=r"(r[2]), "=r"(r[3]) : "r"(addr));
}

__device__ __forceinline__ void mma_bf16(float* d, const unsigned* a, const unsigned* b) {
    asm volatile(
        "mma.sync.aligned.m16n8k16.row.col.f32.bf16.bf16.f32 "
        "{%0,%1,%2,%3}, {%4,%5,%6,%7}, {%8,%9}, {%0,%1,%2,%3};\n"
        : "+f"(d[0]), "+f"(d[1]), "+f"(d[2]), "+f"(d[3])
        : "r"(a[0]), "r"(a[1]), "r"(a[2]), "r"(a[3]), "r"(b[0]), "r"(b[1]));
}

// ---------------- split-bf16 tensor-core GEMM ----------------
// C[M,Nd] = A[M,K] @ B[K,Nd], fp32 in/out, ~2e-5 accuracy (3x bf16 passes).
// Block tile 64 x BN, BK=32, 256 threads, 8 warps (2 in M x 4 in N).
// Warp tile 32 x (BN/4). ldmatrix fragment loads (conflict-free padded smem).
template <int BN>
__device__ __forceinline__ void gemm_bf16_body(const float* __restrict__ A,
                                               const float* __restrict__ B,
                                               float* __restrict__ C,
                                               int M, int K, int Nd) {
    constexpr int BK = 32;
    constexpr int AP = 40;           // A row stride (bf16): 80B, odd 16B-units
    constexpr int BP = BN + 8;       // B row stride (bf16): odd 16B-units
    constexpr int NT = BN / 32;      // n8 tiles per warp

    __shared__ __align__(16) unsigned short Ah[64][AP], Al[64][AP];
    __shared__ __align__(16) unsigned short Bh[BK][BP], Bl[BK][BP];

    const int tid = threadIdx.x;
    const int lane = tid & 31;
    const int warp = tid >> 5;
    const int wm = warp >> 2;         // 0..1 (M)
    const int wn = warp & 3;          // 0..3 (N)
    const int g = lane >> 2;
    const int t4 = lane & 3;
    const int rowBase = blockIdx.x * 64;
    const int colBase = blockIdx.y * BN;

    float acc[2][NT][4];
#pragma unroll
    for (int mt = 0; mt < 2; mt++)
#pragma unroll
        for (int nt = 0; nt < NT; nt++)
#pragma unroll
            for (int i = 0; i < 4; i++) acc[mt][nt][i] = 0.0f;

    // A load mapping: 64 rows x 32 cols, 4 threads/row, 8 floats/thread
    const int ar = tid >> 2;
    const int ac = (tid & 3) * 8;
    // B load mapping: 32 rows x BN cols, 8 threads/row, BN/8 floats/thread
    constexpr int BPT = BN / 8;       // floats per thread (16 or 8)
    const int bk = tid >> 3;
    const int bn = (tid & 7) * BPT;

    for (int k0 = 0; k0 < K; k0 += BK) {
        // ---- A tile: load, split, store packed ----
        {
            int gr = rowBase + ar;
            float4 v0 = make_float4(0.f, 0.f, 0.f, 0.f), v1 = v0;
            if (gr < M) {
                const float* p = &A[(size_t)gr * K + k0 + ac];
                v0 = *(const float4*)p;
                v1 = *(const float4*)(p + 4);
            }
            float f[8] = {v0.x, v0.y, v0.z, v0.w, v1.x, v1.y, v1.z, v1.w};
            unsigned short h[8], l[8];
#pragma unroll
            for (int i = 0; i < 8; i++) bf_split(f[i], h[i], l[i]);
            uint4 uh = make_uint4(pack2(h[0], h[1]), pack2(h[2], h[3]),
                                  pack2(h[4], h[5]), pack2(h[6], h[7]));
            uint4 ul = make_uint4(pack2(l[0], l[1]), pack2(l[2], l[3]),
                                  pack2(l[4], l[5]), pack2(l[6], l[7]));
            *(uint4*)&Ah[ar][ac] = uh;
            *(uint4*)&Al[ar][ac] = ul;
        }
        // ---- B tile ----
        {
#pragma unroll
            for (int q = 0; q < BPT / 8; q++) {
                const float* p = &B[(size_t)(k0 + bk) * Nd + colBase + bn + q * 8];
                float4 v0 = *(const float4*)p;
                float4 v1 = *(const float4*)(p + 4);
                float f[8] = {v0.x, v0.y, v0.z, v0.w, v1.x, v1.y, v1.z, v1.w};
                unsigned short h[8], l[8];
#pragma unroll
                for (int i = 0; i < 8; i++) bf_split(f[i], h[i], l[i]);
                uint4 uh = make_uint4(pack2(h[0], h[1]), pack2(h[2], h[3]),
                                      pack2(h[4], h[5]), pack2(h[6], h[7]));
                uint4 ul = make_uint4(pack2(l[0], l[1]), pack2(l[2], l[3]),
                                      pack2(l[4], l[5]), pack2(l[6], l[7]));
                *(uint4*)&Bh[bk][bn + q * 8] = uh;
                *(uint4*)&Bl[bk][bn + q * 8] = ul;
            }
        }
        __syncthreads();

#pragma unroll
        for (int ks = 0; ks < 2; ks++) {
            const int kk = ks * 16;
            unsigned a_h[2][4], a_l[2][4];
#pragma unroll
            for (int mt = 0; mt < 2; mt++) {
                int r = wm * 32 + mt * 16 + (lane & 15);
                int c = kk + (lane >> 4) * 8;
                ldsm_x4(a_h[mt], smem_u32(&Ah[r][c]));
                ldsm_x4(a_l[mt], smem_u32(&Al[r][c]));
            }
            unsigned b_h[NT][2], b_l[NT][2];
#pragma unroll
            for (int p = 0; p < NT / 2; p++) {
                int k = kk + (lane & 15);
                int n = wn * (BN / 4) + p * 16 + (lane >> 4) * 8;
                unsigned th[4], tl[4];
                ldsm_x4_t(th, smem_u32(&Bh[k][n]));
                ldsm_x4_t(tl, smem_u32(&Bl[k][n]));
                b_h[2 * p][0] = th[0]; b_h[2 * p][1] = th[1];
                b_h[2 * p + 1][0] = th[2]; b_h[2 * p + 1][1] = th[3];
                b_l[2 * p][0] = tl[0]; b_l[2 * p][1] = tl[1];
                b_l[2 * p + 1][0] = tl[2]; b_l[2 * p + 1][1] = tl[3];
            }
#pragma unroll
            for (int mt = 0; mt < 2; mt++)
#pragma unroll
                for (int nt = 0; nt < NT; nt++) {
                    mma_bf16(acc[mt][nt], a_h[mt], b_h[nt]);   // hi*hi
                    mma_bf16(acc[mt][nt], a_h[mt], b_l[nt]);   // hi*lo
                    mma_bf16(acc[mt][nt], a_l[mt], b_h[nt]);   // lo*hi
                }
        }
        __syncthreads();
    }

    // ---- epilogue ----
#pragma unroll
    for (int mt = 0; mt < 2; mt++) {
        int r0 = rowBase + wm * 32 + mt * 16 + g;
#pragma unroll
        for (int nt = 0; nt < NT; nt++) {
            int cn = colBase + wn * (BN / 4) + nt * 8 + t4 * 2;
            if (r0 < M)
                *(float2*)&C[(size_t)r0 * Nd + cn] = make_float2(acc[mt][nt][0], acc[mt][nt][1]);
            if (r0 + 8 < M)
                *(float2*)&C[(size_t)(r0 + 8) * Nd + cn] = make_float2(acc[mt][nt][2], acc[mt][nt][3]);
        }
    }
}

__global__ __launch_bounds__(256) void k_gemm1(const float* __restrict__ x,
                                               const float* __restrict__ W1) {
    gemm_bf16_body<128>(x, W1, g_H1, Nn, IN_DIM, HIDD);
}

__global__ __launch_bounds__(256) void k_gemm2(const float* __restrict__ W2) {
    gemm_bf16_body<64>(g_S1, W2, g_H2, Nn, HIDD, OUTD);
}

// ---------------- SpMM 1: S1 = relu(csr_spmm(H1) + b1), 1 block/row, float2 lanes --------
__global__ __launch_bounds__(128) void k_spmm1(const float* __restrict__ b1) {
    int row = blockIdx.x;
    int d2 = threadIdx.x;            // 0..127 -> float2 column
    const float2* H = (const float2*)g_H1;
    int s = g_rowptr[row];
    int e = g_rowptr[row + 1];
    float ax = 0.0f, ay = 0.0f;
    int j = s;
    for (; j + 4 <= e; j += 4) {
        int   c0 = g_ecol[j + 0], c1 = g_ecol[j + 1], c2 = g_ecol[j + 2], c3 = g_ecol[j + 3];
        float v0 = g_eval[j + 0], v1 = g_eval[j + 1], v2 = g_eval[j + 2], v3 = g_eval[j + 3];
        float2 h0 = H[(size_t)c0 * 128 + d2];
        float2 h1 = H[(size_t)c1 * 128 + d2];
        float2 h2 = H[(size_t)c2 * 128 + d2];
        float2 h3 = H[(size_t)c3 * 128 + d2];
        ax = fmaf(v0, h0.x, ax); ay = fmaf(v0, h0.y, ay);
        ax = fmaf(v1, h1.x, ax); ay = fmaf(v1, h1.y, ay);
        ax = fmaf(v2, h2.x, ax); ay = fmaf(v2, h2.y, ay);
        ax = fmaf(v3, h3.x, ax); ay = fmaf(v3, h3.y, ay);
    }
    for (; j < e; j++) {
        float v = g_eval[j];
        float2 h = H[(size_t)g_ecol[j] * 128 + d2];
        ax = fmaf(v, h.x, ax); ay = fmaf(v, h.y, ay);
    }
    float2 bb = ((const float2*)b1)[d2];
    float2 o = make_float2(fmaxf(ax + bb.x, 0.0f), fmaxf(ay + bb.y, 0.0f));
    ((float2*)g_S1)[(size_t)row * 128 + d2] = o;
}

// ---------------- SpMM 2: out = csr_spmm(H2) + b2 ----------------
__global__ __launch_bounds__(256) void k_spmm2(const float* __restrict__ b2,
                                               float* __restrict__ out) {
    int row = blockIdx.x * 4 + (threadIdx.x >> 6);
    int d = threadIdx.x & 63;
    if (row >= Nn) return;
    int s = g_rowptr[row];
    int e = g_rowptr[row + 1];
    float acc = 0.0f;
    int j = s;
    for (; j + 4 <= e; j += 4) {
        int   c0 = g_ecol[j + 0], c1 = g_ecol[j + 1], c2 = g_ecol[j + 2], c3 = g_ecol[j + 3];
        float v0 = g_eval[j + 0], v1 = g_eval[j + 1], v2 = g_eval[j + 2], v3 = g_eval[j + 3];
        acc = fmaf(v0, g_H2[(size_t)c0 * OUTD + d], acc);
        acc = fmaf(v1, g_H2[(size_t)c1 * OUTD + d], acc);
        acc = fmaf(v2, g_H2[(size_t)c2 * OUTD + d], acc);
        acc = fmaf(v3, g_H2[(size_t)c3 * OUTD + d], acc);
    }
    for (; j < e; j++) {
        acc = fmaf(g_eval[j], g_H2[(size_t)g_ecol[j] * OUTD + d], acc);
    }
    out[(size_t)row * OUTD + d] = acc + b2[d];
}

// ---------------- entry point ----------------
extern "C" void kernel_launch(void* const* d_in, const int* in_sizes, int n_in,
                              void* d_out, int out_size) {
    const float* x    = (const float*)d_in[0];
    const int*   rows = (const int*)  d_in[1];
    const int*   cols = (const int*)  d_in[2];
    const float* vals = (const float*)d_in[3];
    const float* W1   = (const float*)d_in[4];
    const float* b1   = (const float*)d_in[5];
    const float* W2   = (const float*)d_in[6];
    const float* b2   = (const float*)d_in[7];
    float* out = (float*)d_out;

    // CSR build
    k_zero_cnt<<<(Nn + 255) / 256, 256>>>();
    k_hist<<<(Ee + 255) / 256, 256>>>(rows);
    k_scan<<<1, 1024>>>();
    k_scatter<<<(Ee + 255) / 256, 256>>>(rows, cols, vals);

    // layer 1
    k_gemm1<<<dim3((Nn + 63) / 64, HIDD / 128), 256>>>(x, W1);
    k_spmm1<<<Nn, 128>>>(b1);

    // layer 2
    k_gemm2<<<dim3((Nn + 63) / 64, 1), 256>>>(W2);
    k_spmm2<<<(Nn + 3) / 4, 256>>>(b2, out);
}

// round 4
// speedup vs baseline: 1.8032x; 1.1522x over previous
#include <cuda_runtime.h>
#include <cuda_bf16.h>

#define Nn      50000
#define Ee      800000
#define IN_DIM  512
#define HIDD    256
#define OUTD    64

// ---------------- scratch (device globals; no allocs allowed) ----------------
__device__ float    g_H1[(size_t)Nn * HIDD];          // x @ W1 (fp32)
__device__ float    g_H2[(size_t)Nn * OUTD];          // S1 @ W2 (fp32)
__device__ unsigned g_xh[(size_t)Nn * IN_DIM / 2];    // x hi plane (bf16 pairs)
__device__ unsigned g_xl[(size_t)Nn * IN_DIM / 2];    // x lo plane
__device__ unsigned g_s1h[(size_t)Nn * HIDD / 2];     // S1 hi plane
__device__ unsigned g_s1l[(size_t)Nn * HIDD / 2];     // S1 lo plane
__device__ unsigned g_w1h[IN_DIM * HIDD / 2];
__device__ unsigned g_w1l[IN_DIM * HIDD / 2];
__device__ unsigned g_w2h[HIDD * OUTD / 2];
__device__ unsigned g_w2l[HIDD * OUTD / 2];
__device__ int      g_cnt[Nn];
__device__ int      g_rowptr[Nn + 1];
__device__ int      g_ecol[Ee];
__device__ float    g_eval[Ee];

// ---------------- helpers ----------------
__device__ __forceinline__ void bf_split(float x, unsigned short& h, unsigned short& l) {
    __nv_bfloat16 hb = __float2bfloat16_rn(x);
    float r = x - __bfloat162float(hb);
    __nv_bfloat16 lb = __float2bfloat16_rn(r);
    h = __bfloat16_as_ushort(hb);
    l = __bfloat16_as_ushort(lb);
}

__device__ __forceinline__ unsigned pack2(unsigned short a, unsigned short b) {
    return (unsigned)a | ((unsigned)b << 16);
}

__device__ __forceinline__ unsigned smem_u32(const void* p) {
    return (unsigned)__cvta_generic_to_shared(p);
}

__device__ __forceinline__ void cpa16(unsigned dst, const void* src, bool pred) {
    int sz = pred ? 16 : 0;
    asm volatile("cp.async.cg.shared.global [%0], [%1], 16, %2;\n"
                 :: "r"(dst), "l"(src), "r"(sz));
}

__device__ __forceinline__ void cp_commit() { asm volatile("cp.async.commit_group;\n"); }
__device__ __forceinline__ void cp_wait1()  { asm volatile("cp.async.wait_group 1;\n"); }
__device__ __forceinline__ void cp_wait0()  { asm volatile("cp.async.wait_group 0;\n"); }

__device__ __forceinline__ void ldsm_x4(unsigned* r, unsigned addr) {
    asm volatile("ldmatrix.sync.aligned.m8n8.x4.shared.b16 {%0,%1,%2,%3}, [%4];"
                 : "=r"(r[0]), "=r"(r[1]), "=r"(r[2]), "=r"(r[3]) : "r"(addr));
}

__device__ __forceinline__ void ldsm_x4_t(unsigned* r, unsigned addr) {
    asm volatile("ldmatrix.sync.aligned.m8n8.x4.trans.shared.b16 {%0,%1,%2,%3}, [%4];"
                 : "=r"(r[0]), "=r"(r[1]), "=r"(r[2]), "=r"(r[3]) : "r"(addr));
}

__device__ __forceinline__ void mma_bf16(float* d, const unsigned* a, const unsigned* b) {
    asm volatile(
        "mma.sync.aligned.m16n8k16.row.col.f32.bf16.bf16.f32 "
        "{%0,%1,%2,%3}, {%4,%5,%6,%7}, {%8,%9}, {%0,%1,%2,%3};\n"
        : "+f"(d[0]), "+f"(d[1]), "+f"(d[2]), "+f"(d[3])
        : "r"(a[0]), "r"(a[1]), "r"(a[2]), "r"(a[3]), "r"(b[0]), "r"(b[1]));
}

// ---------------- fp32 -> split bf16 planes ----------------
__global__ void k_cvt(const float* __restrict__ in, unsigned* __restrict__ hi,
                      unsigned* __restrict__ lo, int n8) {
    int i = blockIdx.x * blockDim.x + threadIdx.x;
    if (i >= n8) return;
    float4 a = ((const float4*)in)[2 * i];
    float4 b = ((const float4*)in)[2 * i + 1];
    float f[8] = {a.x, a.y, a.z, a.w, b.x, b.y, b.z, b.w};
    unsigned short h[8], l[8];
#pragma unroll
    for (int j = 0; j < 8; j++) bf_split(f[j], h[j], l[j]);
    ((uint4*)hi)[i] = make_uint4(pack2(h[0], h[1]), pack2(h[2], h[3]),
                                 pack2(h[4], h[5]), pack2(h[6], h[7]));
    ((uint4*)lo)[i] = make_uint4(pack2(l[0], l[1]), pack2(l[2], l[3]),
                                 pack2(l[4], l[5]), pack2(l[6], l[7]));
}

// ---------------- CSR build ----------------
__global__ void k_zero_cnt() {
    int i = blockIdx.x * blockDim.x + threadIdx.x;
    if (i < Nn) g_cnt[i] = 0;
}

__global__ void k_hist(const int* __restrict__ rows) {
    int e = blockIdx.x * blockDim.x + threadIdx.x;
    if (e < Ee) atomicAdd(&g_cnt[rows[e]], 1);
}

__global__ void k_scan() {
    const int T = 1024;
    const int ITEMS = (Nn + T - 1) / T;
    __shared__ int sA[T], sB[T];
    int tid = threadIdx.x;
    int base = tid * ITEMS;
    int sum = 0;
    for (int i = 0; i < ITEMS; i++) {
        int idx = base + i;
        if (idx < Nn) sum += g_cnt[idx];
    }
    sA[tid] = sum;
    __syncthreads();
    int* in = sA; int* out = sB;
    for (int off = 1; off < T; off <<= 1) {
        out[tid] = in[tid] + (tid >= off ? in[tid - off] : 0);
        __syncthreads();
        int* t = in; in = out; out = t;
    }
    int run = (tid == 0) ? 0 : in[tid - 1];
    for (int i = 0; i < ITEMS; i++) {
        int idx = base + i;
        if (idx < Nn) {
            g_rowptr[idx] = run;
            run += g_cnt[idx];
            g_cnt[idx] = 0;
        }
    }
    if (tid == T - 1) g_rowptr[Nn] = Ee;
}

__global__ void k_scatter(const int* __restrict__ rows,
                          const int* __restrict__ cols,
                          const float* __restrict__ vals) {
    int e = blockIdx.x * blockDim.x + threadIdx.x;
    if (e >= Ee) return;
    int r = rows[e];
    int pos = g_rowptr[r] + atomicAdd(&g_cnt[r], 1);
    g_ecol[pos] = cols[e];
    g_eval[pos] = vals[e];
}

// ---------------- double-buffered split-bf16 tensor GEMM ----------------
// C[M,Nd] = A @ B from preconverted bf16 hi/lo planes. BM=128, BK=32, 256 thr.
template <int BN, int WM, int WN>
__device__ __forceinline__ void gemm_planes(const unsigned short* __restrict__ Ahg,
                                            const unsigned short* __restrict__ Alg,
                                            const unsigned short* __restrict__ Bhg,
                                            const unsigned short* __restrict__ Blg,
                                            float* __restrict__ C,
                                            int M, int K, int Nd) {
    constexpr int BM = 128, BK = 32;
    constexpr int AP = 40;           // A smem row stride (bf16): 80B = 5x16B (odd)
    constexpr int BP = BN + 8;       // B smem row stride (odd 16B units)
    constexpr int MT = (BM / WM) / 16;
    constexpr int NT = (BN / WN) / 8;

    extern __shared__ unsigned short sm[];
    unsigned short* Ah = sm;
    unsigned short* Al = Ah + 2 * BM * AP;
    unsigned short* Bh = Al + 2 * BM * AP;
    unsigned short* Bl = Bh + 2 * BK * BP;

    const int tid = threadIdx.x;
    const int lane = tid & 31;
    const int warp = tid >> 5;
    const int wm = warp / WN;
    const int wn = warp % WN;
    const int g = lane >> 2;
    const int t4 = lane & 3;
    const int rowBase = blockIdx.x * BM;
    const int colBase = blockIdx.y * BN;

    float acc[MT][NT][4];
#pragma unroll
    for (int mt = 0; mt < MT; mt++)
#pragma unroll
        for (int nt = 0; nt < NT; nt++)
#pragma unroll
            for (int i = 0; i < 4; i++) acc[mt][nt][i] = 0.0f;

    // cp.async mappings
    constexpr int ACH = BK / 8;               // 16B chunks per A row (4)
    constexpr int A_ITERS = BM * ACH / 256;   // 2
    constexpr int BCH = BN / 8;               // chunks per B row
    constexpr int B_ITERS = BK * BCH / 256;   // 2 (BN=128) or 1 (BN=64)

    auto issue = [&](int t, int stage) {
        int k0 = t * BK;
        unsigned aoff = stage * BM * AP;
        unsigned boff = stage * BK * BP;
#pragma unroll
        for (int it = 0; it < A_ITERS; it++) {
            int slot = tid + it * 256;
            int r = slot >> 2, ch = slot & 3;
            int gr = rowBase + r;
            bool p = gr < M;
            size_t go = (size_t)gr * K + k0 + ch * 8;
            unsigned d = smem_u32(&Ah[aoff + r * AP + ch * 8]);
            cpa16(d, Ahg + go, p);
            unsigned d2 = smem_u32(&Al[aoff + r * AP + ch * 8]);
            cpa16(d2, Alg + go, p);
        }
#pragma unroll
        for (int it = 0; it < B_ITERS; it++) {
            int slot = tid + it * 256;
            int r = slot / BCH, ch = slot % BCH;
            size_t go = (size_t)(k0 + r) * Nd + colBase + ch * 8;
            unsigned d = smem_u32(&Bh[boff + r * BP + ch * 8]);
            cpa16(d, Bhg + go, true);
            unsigned d2 = smem_u32(&Bl[boff + r * BP + ch * 8]);
            cpa16(d2, Blg + go, true);
        }
        cp_commit();
    };

    const int T = K / BK;
    issue(0, 0);

    for (int t = 0; t < T; t++) {
        int stage = t & 1;
        if (t + 1 < T) {
            issue(t + 1, stage ^ 1);
            cp_wait1();
        } else {
            cp_wait0();
        }
        __syncthreads();

        unsigned aoff = stage * BM * AP;
        unsigned boff = stage * BK * BP;
#pragma unroll
        for (int ks = 0; ks < 2; ks++) {
            const int kk = ks * 16;
            unsigned a_h[MT][4], a_l[MT][4];
#pragma unroll
            for (int mt = 0; mt < MT; mt++) {
                int r = wm * (BM / WM) + mt * 16 + (lane & 15);
                int c = kk + (lane >> 4) * 8;
                ldsm_x4(a_h[mt], smem_u32(&Ah[aoff + r * AP + c]));
                ldsm_x4(a_l[mt], smem_u32(&Al[aoff + r * AP + c]));
            }
            unsigned b_h[NT][2], b_l[NT][2];
#pragma unroll
            for (int p = 0; p < NT / 2; p++) {
                int k = kk + (lane & 15);
                int n = wn * (BN / WN) + p * 16 + (lane >> 4) * 8;
                unsigned th[4], tl[4];
                ldsm_x4_t(th, smem_u32(&Bh[boff + k * BP + n]));
                ldsm_x4_t(tl, smem_u32(&Bl[boff + k * BP + n]));
                b_h[2 * p][0] = th[0]; b_h[2 * p][1] = th[1];
                b_h[2 * p + 1][0] = th[2]; b_h[2 * p + 1][1] = th[3];
                b_l[2 * p][0] = tl[0]; b_l[2 * p][1] = tl[1];
                b_l[2 * p + 1][0] = tl[2]; b_l[2 * p + 1][1] = tl[3];
            }
#pragma unroll
            for (int mt = 0; mt < MT; mt++)
#pragma unroll
                for (int nt = 0; nt < NT; nt++) {
                    mma_bf16(acc[mt][nt], a_h[mt], b_h[nt]);
                    mma_bf16(acc[mt][nt], a_h[mt], b_l[nt]);
                    mma_bf16(acc[mt][nt], a_l[mt], b_h[nt]);
                }
        }
        __syncthreads();
    }

    // epilogue
#pragma unroll
    for (int mt = 0; mt < MT; mt++) {
        int r0 = rowBase + wm * (BM / WM) + mt * 16 + g;
#pragma unroll
        for (int nt = 0; nt < NT; nt++) {
            int cn = colBase + wn * (BN / WN) + nt * 8 + t4 * 2;
            if (r0 < M)
                *(float2*)&C[(size_t)r0 * Nd + cn] = make_float2(acc[mt][nt][0], acc[mt][nt][1]);
            if (r0 + 8 < M)
                *(float2*)&C[(size_t)(r0 + 8) * Nd + cn] = make_float2(acc[mt][nt][2], acc[mt][nt][3]);
        }
    }
}

__global__ __launch_bounds__(256) void k_gemm1() {
    gemm_planes<128, 2, 4>((const unsigned short*)g_xh, (const unsigned short*)g_xl,
                           (const unsigned short*)g_w1h, (const unsigned short*)g_w1l,
                           g_H1, Nn, IN_DIM, HIDD);
}

__global__ __launch_bounds__(256) void k_gemm2() {
    gemm_planes<64, 4, 2>((const unsigned short*)g_s1h, (const unsigned short*)g_s1l,
                          (const unsigned short*)g_w2h, (const unsigned short*)g_w2l,
                          g_H2, Nn, HIDD, OUTD);
}

// ---------------- SpMM 1: S1 = relu(csr_spmm(H1)+b1) -> split bf16 planes ----------------
__global__ __launch_bounds__(128) void k_spmm1(const float* __restrict__ b1) {
    int row = blockIdx.x;
    int d2 = threadIdx.x;            // float2 column 0..127
    const float2* H = (const float2*)g_H1;
    int s = g_rowptr[row];
    int e = g_rowptr[row + 1];
    float ax = 0.0f, ay = 0.0f;
    int j = s;
    for (; j + 4 <= e; j += 4) {
        int   c0 = g_ecol[j + 0], c1 = g_ecol[j + 1], c2 = g_ecol[j + 2], c3 = g_ecol[j + 3];
        float v0 = g_eval[j + 0], v1 = g_eval[j + 1], v2 = g_eval[j + 2], v3 = g_eval[j + 3];
        float2 h0 = H[(size_t)c0 * 128 + d2];
        float2 h1 = H[(size_t)c1 * 128 + d2];
        float2 h2 = H[(size_t)c2 * 128 + d2];
        float2 h3 = H[(size_t)c3 * 128 + d2];
        ax = fmaf(v0, h0.x, ax); ay = fmaf(v0, h0.y, ay);
        ax = fmaf(v1, h1.x, ax); ay = fmaf(v1, h1.y, ay);
        ax = fmaf(v2, h2.x, ax); ay = fmaf(v2, h2.y, ay);
        ax = fmaf(v3, h3.x, ax); ay = fmaf(v3, h3.y, ay);
    }
    for (; j < e; j++) {
        float v = g_eval[j];
        float2 h = H[(size_t)g_ecol[j] * 128 + d2];
        ax = fmaf(v, h.x, ax); ay = fmaf(v, h.y, ay);
    }
    float2 bb = ((const float2*)b1)[d2];
    float ox = fmaxf(ax + bb.x, 0.0f);
    float oy = fmaxf(ay + bb.y, 0.0f);
    unsigned short hx, lx, hy, ly;
    bf_split(ox, hx, lx);
    bf_split(oy, hy, ly);
    size_t o = (size_t)row * 128 + d2;
    g_s1h[o] = pack2(hx, hy);
    g_s1l[o] = pack2(lx, ly);
}

// ---------------- SpMM 2: out = csr_spmm(H2) + b2 ----------------
__global__ __launch_bounds__(256) void k_spmm2(const float* __restrict__ b2,
                                               float* __restrict__ out) {
    int row = blockIdx.x * 4 + (threadIdx.x >> 6);
    int d = threadIdx.x & 63;
    if (row >= Nn) return;
    int s = g_rowptr[row];
    int e = g_rowptr[row + 1];
    float acc = 0.0f;
    int j = s;
    for (; j + 4 <= e; j += 4) {
        int   c0 = g_ecol[j + 0], c1 = g_ecol[j + 1], c2 = g_ecol[j + 2], c3 = g_ecol[j + 3];
        float v0 = g_eval[j + 0], v1 = g_eval[j + 1], v2 = g_eval[j + 2], v3 = g_eval[j + 3];
        acc = fmaf(v0, g_H2[(size_t)c0 * OUTD + d], acc);
        acc = fmaf(v1, g_H2[(size_t)c1 * OUTD + d], acc);
        acc = fmaf(v2, g_H2[(size_t)c2 * OUTD + d], acc);
        acc = fmaf(v3, g_H2[(size_t)c3 * OUTD + d], acc);
    }
    for (; j < e; j++) {
        acc = fmaf(g_eval[j], g_H2[(size_t)g_ecol[j] * OUTD + d], acc);
    }
    out[(size_t)row * OUTD + d] = acc + b2[d];
}

// ---------------- entry point ----------------
extern "C" void kernel_launch(void* const* d_in, const int* in_sizes, int n_in,
                              void* d_out, int out_size) {
    const float* x    = (const float*)d_in[0];
    const int*   rows = (const int*)  d_in[1];
    const int*   cols = (const int*)  d_in[2];
    const float* vals = (const float*)d_in[3];
    const float* W1   = (const float*)d_in[4];
    const float* b1   = (const float*)d_in[5];
    const float* W2   = (const float*)d_in[6];
    const float* b2   = (const float*)d_in[7];
    float* out = (float*)d_out;

    // dynamic smem sizes (ushorts -> bytes)
    const int smem1 = (2 * 128 * 40 * 2 + 2 * 32 * (128 + 8) * 2) * 2;  // 75776
    const int smem2 = (2 * 128 * 40 * 2 + 2 * 32 * (64 + 8) * 2) * 2;   // 59392
    static int attr_done = 0;
    cudaFuncSetAttribute(k_gemm1, cudaFuncAttributeMaxDynamicSharedMemorySize, smem1);
    cudaFuncSetAttribute(k_gemm2, cudaFuncAttributeMaxDynamicSharedMemorySize, smem2);
    (void)attr_done;

    unsigned *xh, *xl, *w1h, *w1l, *w2h, *w2l;
    cudaGetSymbolAddress((void**)&xh,  g_xh);
    cudaGetSymbolAddress((void**)&xl,  g_xl);
    cudaGetSymbolAddress((void**)&w1h, g_w1h);
    cudaGetSymbolAddress((void**)&w1l, g_w1l);
    cudaGetSymbolAddress((void**)&w2h, g_w2h);
    cudaGetSymbolAddress((void**)&w2l, g_w2l);

    // conversions (independent of CSR build)
    k_cvt<<<(Nn * IN_DIM / 8 + 255) / 256, 256>>>(x,  xh,  xl,  Nn * IN_DIM / 8);
    k_cvt<<<(IN_DIM * HIDD / 8 + 255) / 256, 256>>>(W1, w1h, w1l, IN_DIM * HIDD / 8);
    k_cvt<<<(HIDD * OUTD / 8 + 255) / 256, 256>>>(W2, w2h, w2l, HIDD * OUTD / 8);

    // CSR build
    k_zero_cnt<<<(Nn + 255) / 256, 256>>>();
    k_hist<<<(Ee + 255) / 256, 256>>>(rows);
    k_scan<<<1, 1024>>>();
    k_scatter<<<(Ee + 255) / 256, 256>>>(rows, cols, vals);

    // layer 1
    k_gemm1<<<dim3((Nn + 127) / 128, HIDD / 128), 256, smem1>>>();
    k_spmm1<<<Nn, 128>>>(b1);

    // layer 2
    k_gemm2<<<dim3((Nn + 127) / 128, 1), 256, smem2>>>();
    k_spmm2<<<(Nn + 3) / 4, 256>>>(b2, out);
}

// round 6
// speedup vs baseline: 1.8377x; 1.0191x over previous
#include <cuda_runtime.h>
#include <cuda_bf16.h>
#include <cuda_fp16.h>

#define Nn      50000
#define Ee      800000
#define IN_DIM  512
#define HIDD    256
#define OUTD    64

typedef unsigned short u16;
typedef unsigned int   u32;

// ---------------- scratch (device globals; no allocs allowed) ----------------
__device__ __half    g_H1[(size_t)Nn * HIDD];         // x @ W1 (fp16)
__device__ __half    g_H2[(size_t)Nn * OUTD];         // S1 @ W2 (fp16)
__device__ unsigned  g_xh[(size_t)Nn * IN_DIM / 2];   // x hi plane (bf16 pairs)
__device__ unsigned  g_xl[(size_t)Nn * IN_DIM / 2];
__device__ unsigned  g_s1h[(size_t)Nn * HIDD / 2];    // S1 hi plane
__device__ unsigned  g_s1l[(size_t)Nn * HIDD / 2];
__device__ unsigned  g_w1h[IN_DIM * HIDD / 2];
__device__ unsigned  g_w1l[IN_DIM * HIDD / 2];
__device__ unsigned  g_w2h[HIDD * OUTD / 2];
__device__ unsigned  g_w2l[HIDD * OUTD / 2];
__device__ int       g_cnt[Nn];
__device__ int       g_rowptr[Nn + 1];
__device__ int       g_ecol[Ee];
__device__ float     g_eval[Ee];

// ---------------- helpers ----------------
__device__ __forceinline__ void bf_split(float x, u16& h, u16& l) {
    __nv_bfloat16 hb = __float2bfloat16_rn(x);
    float r = x - __bfloat162float(hb);
    __nv_bfloat16 lb = __float2bfloat16_rn(r);
    h = __bfloat16_as_ushort(hb);
    l = __bfloat16_as_ushort(lb);
}

__device__ __forceinline__ unsigned pack2(u16 a, u16 b) {
    return (unsigned)a | ((unsigned)b << 16);
}

__device__ __forceinline__ u32 smem_u32(const void* p) {
    return (u32)__cvta_generic_to_shared(p);
}

__device__ __forceinline__ void cpa16(u32 dst, const void* src, bool pred) {
    int sz = pred ? 16 : 0;
    asm volatile("cp.async.cg.shared.global [%0], [%1], 16, %2;\n"
                 :: "r"(dst), "l"(src), "r"(sz));
}
__device__ __forceinline__ void cp_commit() { asm volatile("cp.async.commit_group;\n"); }
__device__ __forceinline__ void cp_wait2()  { asm volatile("cp.async.wait_group 2;\n"); }
__device__ __forceinline__ void cp_wait1()  { asm volatile("cp.async.wait_group 1;\n"); }
__device__ __forceinline__ void cp_wait0()  { asm volatile("cp.async.wait_group 0;\n"); }

__device__ __forceinline__ void ldsm_x4(unsigned* r, unsigned addr) {
    asm volatile("ldmatrix.sync.aligned.m8n8.x4.shared.b16 {%0,%1,%2,%3}, [%4];"
                 : "=r"(r[0]), "=r"(r[1]), "=r"(r[2]), "=r"(r[3]) : "r"(addr));
}

__device__ __forceinline__ void ldsm_x4_t(unsigned* r, unsigned addr) {
    asm volatile("ldmatrix.sync.aligned.m8n8.x4.trans.shared.b16 {%0,%1,%2,%3}, [%4];"
                 : "=r"(r[0]), "=r"(r[1]), "=r"(r[2]), "=r"(r[3]) : "r"(addr));
}

__device__ __forceinline__ void mma_bf16(float* d, const unsigned* a, const unsigned* b) {
    asm volatile(
        "mma.sync.aligned.m16n8k16.row.col.f32.bf16.bf16.f32 "
        "{%0,%1,%2,%3}, {%4,%5,%6,%7}, {%8,%9}, {%0,%1,%2,%3};\n"
        : "+f"(d[0]), "+f"(d[1]), "+f"(d[2]), "+f"(d[3])
        : "r"(a[0]), "r"(a[1]), "r"(a[2]), "r"(a[3]), "r"(b[0]), "r"(b[1]));
}

// ---------------- fp32 -> split bf16 planes ----------------
__global__ void k_cvt(const float* __restrict__ in, unsigned* __restrict__ hi,
                      unsigned* __restrict__ lo, int n8) {
    int i = blockIdx.x * blockDim.x + threadIdx.x;
    if (i >= n8) return;
    float4 a = ((const float4*)in)[2 * i];
    float4 b = ((const float4*)in)[2 * i + 1];
    float f[8] = {a.x, a.y, a.z, a.w, b.x, b.y, b.z, b.w};
    u16 h[8], l[8];
#pragma unroll
    for (int j = 0; j < 8; j++) bf_split(f[j], h[j], l[j]);
    ((uint4*)hi)[i] = make_uint4(pack2(h[0], h[1]), pack2(h[2], h[3]),
                                 pack2(h[4], h[5]), pack2(h[6], h[7]));
    ((uint4*)lo)[i] = make_uint4(pack2(l[0], l[1]), pack2(l[2], l[3]),
                                 pack2(l[4], l[5]), pack2(l[6], l[7]));
}

// ---------------- CSR build ----------------
__global__ void k_zero_cnt() {
    int i = blockIdx.x * blockDim.x + threadIdx.x;
    if (i < Nn) g_cnt[i] = 0;
}

__global__ void k_hist(const int* __restrict__ rows) {
    int e = blockIdx.x * blockDim.x + threadIdx.x;
    if (e < Ee) atomicAdd(&g_cnt[rows[e]], 1);
}

__global__ void k_scan() {
    const int T = 1024;
    const int ITEMS = (Nn + T - 1) / T;
    __shared__ int sA[T], sB[T];
    int tid = threadIdx.x;
    int base = tid * ITEMS;
    int sum = 0;
    for (int i = 0; i < ITEMS; i++) {
        int idx = base + i;
        if (idx < Nn) sum += g_cnt[idx];
    }
    sA[tid] = sum;
    __syncthreads();
    int* in = sA; int* out = sB;
    for (int off = 1; off < T; off <<= 1) {
        out[tid] = in[tid] + (tid >= off ? in[tid - off] : 0);
        __syncthreads();
        int* t = in; in = out; out = t;
    }
    int run = (tid == 0) ? 0 : in[tid - 1];
    for (int i = 0; i < ITEMS; i++) {
        int idx = base + i;
        if (idx < Nn) {
            g_rowptr[idx] = run;
            run += g_cnt[idx];
            g_cnt[idx] = 0;
        }
    }
    if (tid == T - 1) g_rowptr[Nn] = Ee;
}

__global__ void k_scatter(const int* __restrict__ rows,
                          const int* __restrict__ cols,
                          const float* __restrict__ vals) {
    int e = blockIdx.x * blockDim.x + threadIdx.x;
    if (e >= Ee) return;
    int r = rows[e];
    int pos = g_rowptr[r] + atomicAdd(&g_cnt[r], 1);
    g_ecol[pos] = cols[e];
    g_eval[pos] = vals[e];
}

// ---------------- 3-stage pipelined split-bf16 tensor GEMM, fp16 output ----------------
// BM=128, BK=32, 256 threads, 8 warps (WM in M x WN in N).
template <int BN, int WM, int WN>
__device__ __forceinline__ void gemm_planes(const u16* __restrict__ Ahg,
                                            const u16* __restrict__ Alg,
                                            const u16* __restrict__ Bhg,
                                            const u16* __restrict__ Blg,
                                            __half* __restrict__ C,
                                            int M, int K, int Nd) {
    constexpr int BM = 128, BK = 32;
    constexpr int AP = 40;           // A smem row stride (bf16): 80B, odd 16B units
    constexpr int BP = BN + 8;       // B smem row stride (odd 16B units)
    constexpr int MT = (BM / WM) / 16;
    constexpr int NT = (BN / WN) / 8;
    constexpr int NSTG = 3;
    constexpr int ASTG = BM * AP;    // u16s per A plane per stage
    constexpr int BSTG = BK * BP;

    extern __shared__ u16 sm[];
    u16* Ah = sm;
    u16* Al = Ah + NSTG * ASTG;
    u16* Bh = Al + NSTG * ASTG;
    u16* Bl = Bh + NSTG * BSTG;

    const int tid = threadIdx.x;
    const int lane = tid & 31;
    const int warp = tid >> 5;
    const int wm = warp / WN;
    const int wn = warp % WN;
    const int g = lane >> 2;
    const int t4 = lane & 3;
    const int rowBase = blockIdx.x * BM;
    const int colBase = blockIdx.y * BN;

    float acc[MT][NT][4];
#pragma unroll
    for (int mt = 0; mt < MT; mt++)
#pragma unroll
        for (int nt = 0; nt < NT; nt++)
#pragma unroll
            for (int i = 0; i < 4; i++) acc[mt][nt][i] = 0.0f;

    constexpr int ACH = BK / 8;
    constexpr int A_ITERS = BM * ACH / 256;   // 2
    constexpr int BCH = BN / 8;
    constexpr int B_ITERS = (BK * BCH + 255) / 256;

    auto issue = [&](int t, int stage) {
        int k0 = t * BK;
        unsigned aoff = stage * ASTG;
        unsigned boff = stage * BSTG;
#pragma unroll
        for (int it = 0; it < A_ITERS; it++) {
            int slot = tid + it * 256;
            int r = slot >> 2, ch = slot & 3;
            int gr = rowBase + r;
            bool p = gr < M;
            size_t go = (size_t)gr * K + k0 + ch * 8;
            cpa16(smem_u32(&Ah[aoff + r * AP + ch * 8]), Ahg + go, p);
            cpa16(smem_u32(&Al[aoff + r * AP + ch * 8]), Alg + go, p);
        }
#pragma unroll
        for (int it = 0; it < B_ITERS; it++) {
            int slot = tid + it * 256;
            if (slot < BK * BCH) {
                int r = slot / BCH, ch = slot % BCH;
                size_t go = (size_t)(k0 + r) * Nd + colBase + ch * 8;
                cpa16(smem_u32(&Bh[boff + r * BP + ch * 8]), Bhg + go, true);
                cpa16(smem_u32(&Bl[boff + r * BP + ch * 8]), Blg + go, true);
            }
        }
        cp_commit();
    };

    const int T = K / BK;
    issue(0, 0);
    if (T > 1) issue(1, 1);

    for (int t = 0; t < T; t++) {
        if (t + 2 < T) {
            issue(t + 2, (t + 2) % NSTG);
            cp_wait2();
        } else if (t + 1 < T) {
            cp_wait1();
        } else {
            cp_wait0();
        }
        __syncthreads();

        int stage = t % NSTG;
        unsigned aoff = stage * ASTG;
        unsigned boff = stage * BSTG;
#pragma unroll
        for (int ks = 0; ks < 2; ks++) {
            const int kk = ks * 16;
            unsigned a_h[MT][4], a_l[MT][4];
#pragma unroll
            for (int mt = 0; mt < MT; mt++) {
                int r = wm * (BM / WM) + mt * 16 + (lane & 15);
                int c = kk + (lane >> 4) * 8;
                ldsm_x4(a_h[mt], smem_u32(&Ah[aoff + r * AP + c]));
                ldsm_x4(a_l[mt], smem_u32(&Al[aoff + r * AP + c]));
            }
            unsigned b_h[NT][2], b_l[NT][2];
#pragma unroll
            for (int p = 0; p < NT / 2; p++) {
                int k = kk + (lane & 15);
                int n = wn * (BN / WN) + p * 16 + (lane >> 4) * 8;
                unsigned th[4], tl[4];
                ldsm_x4_t(th, smem_u32(&Bh[boff + k * BP + n]));
                ldsm_x4_t(tl, smem_u32(&Bl[boff + k * BP + n]));
                b_h[2 * p][0] = th[0]; b_h[2 * p][1] = th[1];
                b_h[2 * p + 1][0] = th[2]; b_h[2 * p + 1][1] = th[3];
                b_l[2 * p][0] = tl[0]; b_l[2 * p][1] = tl[1];
                b_l[2 * p + 1][0] = tl[2]; b_l[2 * p + 1][1] = tl[3];
            }
#pragma unroll
            for (int mt = 0; mt < MT; mt++)
#pragma unroll
                for (int nt = 0; nt < NT; nt++) {
                    mma_bf16(acc[mt][nt], a_h[mt], b_h[nt]);
                    mma_bf16(acc[mt][nt], a_h[mt], b_l[nt]);
                    mma_bf16(acc[mt][nt], a_l[mt], b_h[nt]);
                }
        }
        __syncthreads();
    }

    // epilogue: fp16 output
#pragma unroll
    for (int mt = 0; mt < MT; mt++) {
        int r0 = rowBase + wm * (BM / WM) + mt * 16 + g;
#pragma unroll
        for (int nt = 0; nt < NT; nt++) {
            int cn = colBase + wn * (BN / WN) + nt * 8 + t4 * 2;
            if (r0 < M)
                *(__half2*)&C[(size_t)r0 * Nd + cn] =
                    __floats2half2_rn(acc[mt][nt][0], acc[mt][nt][1]);
            if (r0 + 8 < M)
                *(__half2*)&C[(size_t)(r0 + 8) * Nd + cn] =
                    __floats2half2_rn(acc[mt][nt][2], acc[mt][nt][3]);
        }
    }
}

__global__ __launch_bounds__(256) void k_gemm1() {
    gemm_planes<128, 2, 4>((const u16*)g_xh, (const u16*)g_xl,
                           (const u16*)g_w1h, (const u16*)g_w1l,
                           g_H1, Nn, IN_DIM, HIDD);
}

__global__ __launch_bounds__(256) void k_gemm2() {
    gemm_planes<64, 4, 2>((const u16*)g_s1h, (const u16*)g_s1l,
                          (const u16*)g_w2h, (const u16*)g_w2l,
                          g_H2, Nn, HIDD, OUTD);
}

// ---------------- SpMM 1: S1 = relu(csr_spmm(H1)+b1) -> split bf16 planes ----------------
__global__ __launch_bounds__(128) void k_spmm1(const float* __restrict__ b1) {
    int row = blockIdx.x;
    int d2 = threadIdx.x;            // half2 column 0..127
    const __half2* H = (const __half2*)g_H1;
    int s = g_rowptr[row];
    int e = g_rowptr[row + 1];
    float ax = 0.0f, ay = 0.0f;
    int j = s;
    for (; j + 4 <= e; j += 4) {
        int   c0 = g_ecol[j + 0], c1 = g_ecol[j + 1], c2 = g_ecol[j + 2], c3 = g_ecol[j + 3];
        float v0 = g_eval[j + 0], v1 = g_eval[j + 1], v2 = g_eval[j + 2], v3 = g_eval[j + 3];
        float2 h0 = __half22float2(H[(size_t)c0 * 128 + d2]);
        float2 h1 = __half22float2(H[(size_t)c1 * 128 + d2]);
        float2 h2 = __half22float2(H[(size_t)c2 * 128 + d2]);
        float2 h3 = __half22float2(H[(size_t)c3 * 128 + d2]);
        ax = fmaf(v0, h0.x, ax); ay = fmaf(v0, h0.y, ay);
        ax = fmaf(v1, h1.x, ax); ay = fmaf(v1, h1.y, ay);
        ax = fmaf(v2, h2.x, ax); ay = fmaf(v2, h2.y, ay);
        ax = fmaf(v3, h3.x, ax); ay = fmaf(v3, h3.y, ay);
    }
    for (; j < e; j++) {
        float v = g_eval[j];
        float2 h = __half22float2(H[(size_t)g_ecol[j] * 128 + d2]);
        ax = fmaf(v, h.x, ax); ay = fmaf(v, h.y, ay);
    }
    float2 bb = ((const float2*)b1)[d2];
    float ox = fmaxf(ax + bb.x, 0.0f);
    float oy = fmaxf(ay + bb.y, 0.0f);
    u16 hx, lx, hy, ly;
    bf_split(ox, hx, lx);
    bf_split(oy, hy, ly);
    size_t o = (size_t)row * 128 + d2;
    g_s1h[o] = pack2(hx, hy);
    g_s1l[o] = pack2(lx, ly);
}

// ---------------- SpMM 2: out = csr_spmm(H2) + b2, 8 rows/block ----------------
__global__ __launch_bounds__(256) void k_spmm2(const float* __restrict__ b2,
                                               float* __restrict__ out) {
    int row = blockIdx.x * 8 + (threadIdx.x >> 5);
    int d2 = threadIdx.x & 31;       // half2 column 0..31
    if (row >= Nn) return;
    const __half2* H = (const __half2*)g_H2;
    int s = g_rowptr[row];
    int e = g_rowptr[row + 1];
    float ax = 0.0f, ay = 0.0f;
    int j = s;
    for (; j + 4 <= e; j += 4) {
        int   c0 = g_ecol[j + 0], c1 = g_ecol[j + 1], c2 = g_ecol[j + 2], c3 = g_ecol[j + 3];
        float v0 = g_eval[j + 0], v1 = g_eval[j + 1], v2 = g_eval[j + 2], v3 = g_eval[j + 3];
        float2 h0 = __half22float2(H[(size_t)c0 * 32 + d2]);
        float2 h1 = __half22float2(H[(size_t)c1 * 32 + d2]);
        float2 h2 = __half22float2(H[(size_t)c2 * 32 + d2]);
        float2 h3 = __half22float2(H[(size_t)c3 * 32 + d2]);
        ax = fmaf(v0, h0.x, ax); ay = fmaf(v0, h0.y, ay);
        ax = fmaf(v1, h1.x, ax); ay = fmaf(v1, h1.y, ay);
        ax = fmaf(v2, h2.x, ax); ay = fmaf(v2, h2.y, ay);
        ax = fmaf(v3, h3.x, ax); ay = fmaf(v3, h3.y, ay);
    }
    for (; j < e; j++) {
        float v = g_eval[j];
        float2 h = __half22float2(H[(size_t)g_ecol[j] * 32 + d2]);
        ax = fmaf(v, h.x, ax); ay = fmaf(v, h.y, ay);
    }
    float2 bb = ((const float2*)b2)[d2];
    ((float2*)out)[(size_t)row * 32 + d2] = make_float2(ax + bb.x, ay + bb.y);
}

// ---------------- entry point ----------------
extern "C" void kernel_launch(void* const* d_in, const int* in_sizes, int n_in,
                              void* d_out, int out_size) {
    const float* x    = (const float*)d_in[0];
    const int*   rows = (const int*)  d_in[1];
    const int*   cols = (const int*)  d_in[2];
    const float* vals = (const float*)d_in[3];
    const float* W1   = (const float*)d_in[4];
    const float* b1   = (const float*)d_in[5];
    const float* W2   = (const float*)d_in[6];
    const float* b2   = (const float*)d_in[7];
    float* out = (float*)d_out;

    // dynamic smem (u16 counts -> bytes): 3 stages
    const int smem1 = (3 * 128 * 40 * 2 + 3 * 32 * (128 + 8) * 2) * 2;  // 113664
    const int smem2 = (3 * 128 * 40 * 2 + 3 * 32 * (64 + 8) * 2) * 2;   //  89088
    cudaFuncSetAttribute(k_gemm1, cudaFuncAttributeMaxDynamicSharedMemorySize, smem1);
    cudaFuncSetAttribute(k_gemm2, cudaFuncAttributeMaxDynamicSharedMemorySize, smem2);

    unsigned *xh, *xl, *w1h, *w1l, *w2h, *w2l;
    cudaGetSymbolAddress((void**)&xh,  g_xh);
    cudaGetSymbolAddress((void**)&xl,  g_xl);
    cudaGetSymbolAddress((void**)&w1h, g_w1h);
    cudaGetSymbolAddress((void**)&w1l, g_w1l);
    cudaGetSymbolAddress((void**)&w2h, g_w2h);
    cudaGetSymbolAddress((void**)&w2l, g_w2l);

    // conversions
    k_cvt<<<(Nn * IN_DIM / 8 + 255) / 256, 256>>>(x,  xh,  xl,  Nn * IN_DIM / 8);
    k_cvt<<<(IN_DIM * HIDD / 8 + 255) / 256, 256>>>(W1, w1h, w1l, IN_DIM * HIDD / 8);
    k_cvt<<<(HIDD * OUTD / 8 + 255) / 256, 256>>>(W2, w2h, w2l, HIDD * OUTD / 8);

    // CSR build
    k_zero_cnt<<<(Nn + 255) / 256, 256>>>();
    k_hist<<<(Ee + 255) / 256, 256>>>(rows);
    k_scan<<<1, 1024>>>();
    k_scatter<<<(Ee + 255) / 256, 256>>>(rows, cols, vals);

    // layer 1
    k_gemm1<<<dim3((Nn + 127) / 128, HIDD / 128), 256, smem1>>>();
    k_spmm1<<<Nn, 128>>>(b1);

    // layer 2
    k_gemm2<<<dim3((Nn + 127) / 128, 1), 256, smem2>>>();
    k_spmm2<<<(Nn + 7) / 8, 256>>>(b2, out);
}

// round 7
// speedup vs baseline: 1.8764x; 1.0211x over previous
#include <cuda_runtime.h>
#include <cuda_bf16.h>
#include <cuda_fp16.h>

#define Nn      50000
#define Ee      800000
#define IN_DIM  512
#define HIDD    256
#define OUTD    64

typedef unsigned short u16;
typedef unsigned int   u32;

// ---------------- scratch (device globals; no allocs allowed) ----------------
__device__ __half    g_H1[(size_t)Nn * HIDD];         // x @ W1 (fp16)
__device__ __half    g_H2[(size_t)Nn * OUTD];         // S1 @ W2 (fp16)
__device__ unsigned  g_xh[(size_t)Nn * IN_DIM / 2];   // x hi plane (bf16 pairs)
__device__ unsigned  g_xl[(size_t)Nn * IN_DIM / 2];
__device__ unsigned  g_s1h[(size_t)Nn * HIDD / 2];    // S1 hi plane
__device__ unsigned  g_s1l[(size_t)Nn * HIDD / 2];
__device__ unsigned  g_w1h[IN_DIM * HIDD / 2];
__device__ unsigned  g_w1l[IN_DIM * HIDD / 2];
__device__ unsigned  g_w2h[HIDD * OUTD / 2];
__device__ unsigned  g_w2l[HIDD * OUTD / 2];
__device__ int       g_cnt[Nn];
__device__ int       g_rowptr[Nn + 1];
__device__ int       g_ecol[Ee];
__device__ float     g_eval[Ee];

// ---------------- helpers ----------------
__device__ __forceinline__ void bf_split(float x, u16& h, u16& l) {
    __nv_bfloat16 hb = __float2bfloat16_rn(x);
    float r = x - __bfloat162float(hb);
    __nv_bfloat16 lb = __float2bfloat16_rn(r);
    h = __bfloat16_as_ushort(hb);
    l = __bfloat16_as_ushort(lb);
}

__device__ __forceinline__ unsigned pack2(u16 a, u16 b) {
    return (unsigned)a | ((unsigned)b << 16);
}

__device__ __forceinline__ u32 smem_u32(const void* p) {
    return (u32)__cvta_generic_to_shared(p);
}

__device__ __forceinline__ void cpa16(u32 dst, const void* src, bool pred) {
    int sz = pred ? 16 : 0;
    asm volatile("cp.async.cg.shared.global [%0], [%1], 16, %2;\n"
                 :: "r"(dst), "l"(src), "r"(sz));
}
__device__ __forceinline__ void cp_commit() { asm volatile("cp.async.commit_group;\n"); }
__device__ __forceinline__ void cp_wait1()  { asm volatile("cp.async.wait_group 1;\n"); }
__device__ __forceinline__ void cp_wait0()  { asm volatile("cp.async.wait_group 0;\n"); }

__device__ __forceinline__ void ldsm_x4(unsigned* r, unsigned addr) {
    asm volatile("ldmatrix.sync.aligned.m8n8.x4.shared.b16 {%0,%1,%2,%3}, [%4];"
                 : "=r"(r[0]), "=r"(r[1]), "=r"(r[2]), "=r"(r[3]) : "r"(addr));
}

__device__ __forceinline__ void ldsm_x4_t(unsigned* r, unsigned addr) {
    asm volatile("ldmatrix.sync.aligned.m8n8.x4.trans.shared.b16 {%0,%1,%2,%3}, [%4];"
                 : "=r"(r[0]), "=r"(r[1]), "=r"(r[2]), "=r"(r[3]) : "r"(addr));
}

__device__ __forceinline__ void mma_bf16(float* d, const unsigned* a, const unsigned* b) {
    asm volatile(
        "mma.sync.aligned.m16n8k16.row.col.f32.bf16.bf16.f32 "
        "{%0,%1,%2,%3}, {%4,%5,%6,%7}, {%8,%9}, {%0,%1,%2,%3};\n"
        : "+f"(d[0]), "+f"(d[1]), "+f"(d[2]), "+f"(d[3])
        : "r"(a[0]), "r"(a[1]), "r"(a[2]), "r"(a[3]), "r"(b[0]), "r"(b[1]));
}

// ---------------- fp32 -> split bf16 planes ----------------
__global__ void k_cvt(const float* __restrict__ in, unsigned* __restrict__ hi,
                      unsigned* __restrict__ lo, int n8) {
    int i = blockIdx.x * blockDim.x + threadIdx.x;
    if (i >= n8) return;
    float4 a = ((const float4*)in)[2 * i];
    float4 b = ((const float4*)in)[2 * i + 1];
    float f[8] = {a.x, a.y, a.z, a.w, b.x, b.y, b.z, b.w};
    u16 h[8], l[8];
#pragma unroll
    for (int j = 0; j < 8; j++) bf_split(f[j], h[j], l[j]);
    ((uint4*)hi)[i] = make_uint4(pack2(h[0], h[1]), pack2(h[2], h[3]),
                                 pack2(h[4], h[5]), pack2(h[6], h[7]));
    ((uint4*)lo)[i] = make_uint4(pack2(l[0], l[1]), pack2(l[2], l[3]),
                                 pack2(l[4], l[5]), pack2(l[6], l[7]));
}

// ---------------- CSR build ----------------
__global__ void k_hist(const int* __restrict__ rows) {
    int e = blockIdx.x * blockDim.x + threadIdx.x;
    if (e < Ee) atomicAdd(&g_cnt[rows[e]], 1);
}

__global__ void k_scan() {
    const int T = 1024;
    const int ITEMS = (Nn + T - 1) / T;
    __shared__ int sA[T], sB[T];
    int tid = threadIdx.x;
    int base = tid * ITEMS;
    int sum = 0;
    for (int i = 0; i < ITEMS; i++) {
        int idx = base + i;
        if (idx < Nn) sum += g_cnt[idx];
    }
    sA[tid] = sum;
    __syncthreads();
    int* in = sA; int* out = sB;
    for (int off = 1; off < T; off <<= 1) {
        out[tid] = in[tid] + (tid >= off ? in[tid - off] : 0);
        __syncthreads();
        int* t = in; in = out; out = t;
    }
    int run = (tid == 0) ? 0 : in[tid - 1];
    for (int i = 0; i < ITEMS; i++) {
        int idx = base + i;
        if (idx < Nn) {
            g_rowptr[idx] = run;
            run += g_cnt[idx];
            g_cnt[idx] = 0;
        }
    }
    if (tid == T - 1) g_rowptr[Nn] = Ee;
}

__global__ void k_scatter(const int* __restrict__ rows,
                          const int* __restrict__ cols,
                          const float* __restrict__ vals) {
    int e = blockIdx.x * blockDim.x + threadIdx.x;
    if (e >= Ee) return;
    int r = rows[e];
    int pos = g_rowptr[r] + atomicAdd(&g_cnt[r], 1);
    g_ecol[pos] = cols[e];
    g_eval[pos] = vals[e];
}

// ---------------- 2-stage pipelined split-bf16 tensor GEMM, fp16 output ----------------
// BM=128, BK=32, 256 threads, 8 warps (WM in M x WN in N). 75.8KB smem -> 2 CTA/SM.
template <int BN, int WM, int WN>
__device__ __forceinline__ void gemm_planes(const u16* __restrict__ Ahg,
                                            const u16* __restrict__ Alg,
                                            const u16* __restrict__ Bhg,
                                            const u16* __restrict__ Blg,
                                            __half* __restrict__ C,
                                            int M, int K, int Nd) {
    constexpr int BM = 128, BK = 32;
    constexpr int AP = 40;           // A smem row stride (bf16): 80B, odd 16B units
    constexpr int BP = BN + 8;       // B smem row stride (odd 16B units)
    constexpr int MT = (BM / WM) / 16;
    constexpr int NT = (BN / WN) / 8;
    constexpr int ASTG = BM * AP;    // u16s per A plane per stage
    constexpr int BSTG = BK * BP;

    extern __shared__ u16 sm[];
    u16* Ah = sm;
    u16* Al = Ah + 2 * ASTG;
    u16* Bh = Al + 2 * ASTG;
    u16* Bl = Bh + 2 * BSTG;

    const int tid = threadIdx.x;
    const int lane = tid & 31;
    const int warp = tid >> 5;
    const int wm = warp / WN;
    const int wn = warp % WN;
    const int g = lane >> 2;
    const int t4 = lane & 3;
    const int rowBase = blockIdx.x * BM;
    const int colBase = blockIdx.y * BN;

    float acc[MT][NT][4];
#pragma unroll
    for (int mt = 0; mt < MT; mt++)
#pragma unroll
        for (int nt = 0; nt < NT; nt++)
#pragma unroll
            for (int i = 0; i < 4; i++) acc[mt][nt][i] = 0.0f;

    constexpr int ACH = BK / 8;
    constexpr int A_ITERS = BM * ACH / 256;   // 2
    constexpr int BCH = BN / 8;
    constexpr int B_ITERS = (BK * BCH + 255) / 256;

    auto issue = [&](int t, int stage) {
        int k0 = t * BK;
        unsigned aoff = stage * ASTG;
        unsigned boff = stage * BSTG;
#pragma unroll
        for (int it = 0; it < A_ITERS; it++) {
            int slot = tid + it * 256;
            int r = slot >> 2, ch = slot & 3;
            int gr = rowBase + r;
            bool p = gr < M;
            size_t go = (size_t)gr * K + k0 + ch * 8;
            cpa16(smem_u32(&Ah[aoff + r * AP + ch * 8]), Ahg + go, p);
            cpa16(smem_u32(&Al[aoff + r * AP + ch * 8]), Alg + go, p);
        }
#pragma unroll
        for (int it = 0; it < B_ITERS; it++) {
            int slot = tid + it * 256;
            if (slot < BK * BCH) {
                int r = slot / BCH, ch = slot % BCH;
                size_t go = (size_t)(k0 + r) * Nd + colBase + ch * 8;
                cpa16(smem_u32(&Bh[boff + r * BP + ch * 8]), Bhg + go, true);
                cpa16(smem_u32(&Bl[boff + r * BP + ch * 8]), Blg + go, true);
            }
        }
        cp_commit();
    };

    const int T = K / BK;
    issue(0, 0);

    for (int t = 0; t < T; t++) {
        int stage = t & 1;
        if (t + 1 < T) {
            issue(t + 1, stage ^ 1);
            cp_wait1();
        } else {
            cp_wait0();
        }
        __syncthreads();

        unsigned aoff = stage * ASTG;
        unsigned boff = stage * BSTG;
#pragma unroll
        for (int ks = 0; ks < 2; ks++) {
            const int kk = ks * 16;
            unsigned a_h[MT][4], a_l[MT][4];
#pragma unroll
            for (int mt = 0; mt < MT; mt++) {
                int r = wm * (BM / WM) + mt * 16 + (lane & 15);
                int c = kk + (lane >> 4) * 8;
                ldsm_x4(a_h[mt], smem_u32(&Ah[aoff + r * AP + c]));
                ldsm_x4(a_l[mt], smem_u32(&Al[aoff + r * AP + c]));
            }
            unsigned b_h[NT][2], b_l[NT][2];
#pragma unroll
            for (int p = 0; p < NT / 2; p++) {
                int k = kk + (lane & 15);
                int n = wn * (BN / WN) + p * 16 + (lane >> 4) * 8;
                unsigned th[4], tl[4];
                ldsm_x4_t(th, smem_u32(&Bh[boff + k * BP + n]));
                ldsm_x4_t(tl, smem_u32(&Bl[boff + k * BP + n]));
                b_h[2 * p][0] = th[0]; b_h[2 * p][1] = th[1];
                b_h[2 * p + 1][0] = th[2]; b_h[2 * p + 1][1] = th[3];
                b_l[2 * p][0] = tl[0]; b_l[2 * p][1] = tl[1];
                b_l[2 * p + 1][0] = tl[2]; b_l[2 * p + 1][1] = tl[3];
            }
#pragma unroll
            for (int mt = 0; mt < MT; mt++)
#pragma unroll
                for (int nt = 0; nt < NT; nt++) {
                    mma_bf16(acc[mt][nt], a_h[mt], b_h[nt]);
                    mma_bf16(acc[mt][nt], a_h[mt], b_l[nt]);
                    mma_bf16(acc[mt][nt], a_l[mt], b_h[nt]);
                }
        }
        __syncthreads();
    }

    // epilogue: fp16 output
#pragma unroll
    for (int mt = 0; mt < MT; mt++) {
        int r0 = rowBase + wm * (BM / WM) + mt * 16 + g;
#pragma unroll
        for (int nt = 0; nt < NT; nt++) {
            int cn = colBase + wn * (BN / WN) + nt * 8 + t4 * 2;
            if (r0 < M)
                *(__half2*)&C[(size_t)r0 * Nd + cn] =
                    __floats2half2_rn(acc[mt][nt][0], acc[mt][nt][1]);
            if (r0 + 8 < M)
                *(__half2*)&C[(size_t)(r0 + 8) * Nd + cn] =
                    __floats2half2_rn(acc[mt][nt][2], acc[mt][nt][3]);
        }
    }
}

__global__ __launch_bounds__(256, 2) void k_gemm1() {
    gemm_planes<128, 2, 4>((const u16*)g_xh, (const u16*)g_xl,
                           (const u16*)g_w1h, (const u16*)g_w1l,
                           g_H1, Nn, IN_DIM, HIDD);
}

__global__ __launch_bounds__(256, 2) void k_gemm2() {
    gemm_planes<64, 4, 2>((const u16*)g_s1h, (const u16*)g_s1l,
                          (const u16*)g_w2h, (const u16*)g_w2l,
                          g_H2, Nn, HIDD, OUTD);
}

// ---------------- SpMM 1: S1 = relu(csr_spmm(H1)+b1) -> split bf16 planes ----------------
__global__ __launch_bounds__(128) void k_spmm1(const float* __restrict__ b1) {
    int row = blockIdx.x;
    int d2 = threadIdx.x;            // half2 column 0..127
    const __half2* H = (const __half2*)g_H1;
    int s = g_rowptr[row];
    int e = g_rowptr[row + 1];
    float ax = 0.0f, ay = 0.0f;
    int j = s;
    for (; j + 4 <= e; j += 4) {
        int   c0 = g_ecol[j + 0], c1 = g_ecol[j + 1], c2 = g_ecol[j + 2], c3 = g_ecol[j + 3];
        float v0 = g_eval[j + 0], v1 = g_eval[j + 1], v2 = g_eval[j + 2], v3 = g_eval[j + 3];
        float2 h0 = __half22float2(H[(size_t)c0 * 128 + d2]);
        float2 h1 = __half22float2(H[(size_t)c1 * 128 + d2]);
        float2 h2 = __half22float2(H[(size_t)c2 * 128 + d2]);
        float2 h3 = __half22float2(H[(size_t)c3 * 128 + d2]);
        ax = fmaf(v0, h0.x, ax); ay = fmaf(v0, h0.y, ay);
        ax = fmaf(v1, h1.x, ax); ay = fmaf(v1, h1.y, ay);
        ax = fmaf(v2, h2.x, ax); ay = fmaf(v2, h2.y, ay);
        ax = fmaf(v3, h3.x, ax); ay = fmaf(v3, h3.y, ay);
    }
    for (; j < e; j++) {
        float v = g_eval[j];
        float2 h = __half22float2(H[(size_t)g_ecol[j] * 128 + d2]);
        ax = fmaf(v, h.x, ax); ay = fmaf(v, h.y, ay);
    }
    float2 bb = ((const float2*)b1)[d2];
    float ox = fmaxf(ax + bb.x, 0.0f);
    float oy = fmaxf(ay + bb.y, 0.0f);
    u16 hx, lx, hy, ly;
    bf_split(ox, hx, lx);
    bf_split(oy, hy, ly);
    size_t o = (size_t)row * 128 + d2;
    g_s1h[o] = pack2(hx, hy);
    g_s1l[o] = pack2(lx, ly);
}

// ---------------- SpMM 2: out = csr_spmm(H2) + b2, 8 rows/block ----------------
__global__ __launch_bounds__(256) void k_spmm2(const float* __restrict__ b2,
                                               float* __restrict__ out) {
    int row = blockIdx.x * 8 + (threadIdx.x >> 5);
    int d2 = threadIdx.x & 31;       // half2 column 0..31
    if (row >= Nn) return;
    const __half2* H = (const __half2*)g_H2;
    int s = g_rowptr[row];
    int e = g_rowptr[row + 1];
    float ax = 0.0f, ay = 0.0f;
    int j = s;
    for (; j + 4 <= e; j += 4) {
        int   c0 = g_ecol[j + 0], c1 = g_ecol[j + 1], c2 = g_ecol[j + 2], c3 = g_ecol[j + 3];
        float v0 = g_eval[j + 0], v1 = g_eval[j + 1], v2 = g_eval[j + 2], v3 = g_eval[j + 3];
        float2 h0 = __half22float2(H[(size_t)c0 * 32 + d2]);
        float2 h1 = __half22float2(H[(size_t)c1 * 32 + d2]);
        float2 h2 = __half22float2(H[(size_t)c2 * 32 + d2]);
        float2 h3 = __half22float2(H[(size_t)c3 * 32 + d2]);
        ax = fmaf(v0, h0.x, ax); ay = fmaf(v0, h0.y, ay);
        ax = fmaf(v1, h1.x, ax); ay = fmaf(v1, h1.y, ay);
        ax = fmaf(v2, h2.x, ax); ay = fmaf(v2, h2.y, ay);
        ax = fmaf(v3, h3.x, ax); ay = fmaf(v3, h3.y, ay);
    }
    for (; j < e; j++) {
        float v = g_eval[j];
        float2 h = __half22float2(H[(size_t)g_ecol[j] * 32 + d2]);
        ax = fmaf(v, h.x, ax); ay = fmaf(v, h.y, ay);
    }
    float2 bb = ((const float2*)b2)[d2];
    ((float2*)out)[(size_t)row * 32 + d2] = make_float2(ax + bb.x, ay + bb.y);
}

// ---------------- entry point ----------------
extern "C" void kernel_launch(void* const* d_in, const int* in_sizes, int n_in,
                              void* d_out, int out_size) {
    const float* x    = (const float*)d_in[0];
    const int*   rows = (const int*)  d_in[1];
    const int*   cols = (const int*)  d_in[2];
    const float* vals = (const float*)d_in[3];
    const float* W1   = (const float*)d_in[4];
    const float* b1   = (const float*)d_in[5];
    const float* W2   = (const float*)d_in[6];
    const float* b2   = (const float*)d_in[7];
    float* out = (float*)d_out;

    // dynamic smem (u16 counts -> bytes): 2 stages -> 2 CTA/SM
    const int smem1 = (2 * 128 * 40 * 2 + 2 * 32 * (128 + 8) * 2) * 2;  // 75776
    const int smem2 = (2 * 128 * 40 * 2 + 2 * 32 * (64 + 8) * 2) * 2;   // 59392
    cudaFuncSetAttribute(k_gemm1, cudaFuncAttributeMaxDynamicSharedMemorySize, smem1);
    cudaFuncSetAttribute(k_gemm2, cudaFuncAttributeMaxDynamicSharedMemorySize, smem2);

    unsigned *xh, *xl, *w1h, *w1l, *w2h, *w2l;
    cudaGetSymbolAddress((void**)&xh,  g_xh);
    cudaGetSymbolAddress((void**)&xl,  g_xl);
    cudaGetSymbolAddress((void**)&w1h, g_w1h);
    cudaGetSymbolAddress((void**)&w1l, g_w1l);
    cudaGetSymbolAddress((void**)&w2h, g_w2h);
    cudaGetSymbolAddress((void**)&w2l, g_w2l);
    int* cnt;
    cudaGetSymbolAddress((void**)&cnt, g_cnt);

    // conversions first; gemm1 is the 4th KERNEL launch (ncu profiles index 3)
    k_cvt<<<(Nn * IN_DIM / 8 + 255) / 256, 256>>>(x,  xh,  xl,  Nn * IN_DIM / 8);
    k_cvt<<<(IN_DIM * HIDD / 8 + 255) / 256, 256>>>(W1, w1h, w1l, IN_DIM * HIDD / 8);
    k_cvt<<<(HIDD * OUTD / 8 + 255) / 256, 256>>>(W2, w2h, w2l, HIDD * OUTD / 8);

    // layer 1 GEMM
    k_gemm1<<<dim3((Nn + 127) / 128, HIDD / 128), 256, smem1>>>();

    // CSR build (independent of gemm1; needed by spmm1)
    cudaMemsetAsync(cnt, 0, Nn * sizeof(int));
    k_hist<<<(Ee + 255) / 256, 256>>>(rows);
    k_scan<<<1, 1024>>>();
    k_scatter<<<(Ee + 255) / 256, 256>>>(rows, cols, vals);

    // aggregate layer 1
    k_spmm1<<<Nn, 128>>>(b1);

    // layer 2
    k_gemm2<<<dim3((Nn + 127) / 128, 1), 256, smem2>>>();
    k_spmm2<<<(Nn + 7) / 8, 256>>>(b2, out);
}

// round 8
// speedup vs baseline: 2.9312x; 1.5622x over previous
#include <cuda_runtime.h>
#include <cuda_fp16.h>

#define Nn      50000
#define Ee      800000
#define IN_DIM  512
#define HIDD    256
#define OUTD    64

typedef unsigned short u16;
typedef unsigned int   u32;

// ---------------- scratch (device globals; no allocs allowed) ----------------
__device__ __half    g_H1[(size_t)Nn * HIDD];        // x @ W1 (fp16)
__device__ __half    g_H2[(size_t)Nn * OUTD];        // S1 @ W2 (fp16)
__device__ __half    g_x16[(size_t)Nn * IN_DIM];     // x as fp16
__device__ __half    g_s116[(size_t)Nn * HIDD];      // S1 as fp16
__device__ __half    g_w1h[IN_DIM * HIDD];           // W1 hi plane [K][N]
__device__ __half    g_w1l[IN_DIM * HIDD];           // W1 lo plane
__device__ __half    g_w2h[HIDD * OUTD];
__device__ __half    g_w2l[HIDD * OUTD];
__device__ int       g_cnt[Nn];
__device__ int       g_rowptr[Nn + 1];
__device__ int       g_blksum[128];
__device__ int       g_ecol[Ee];
__device__ float     g_eval[Ee];

// ---------------- helpers ----------------
__device__ __forceinline__ u32 smem_u32(const void* p) {
    return (u32)__cvta_generic_to_shared(p);
}

__device__ __forceinline__ void cpa16(u32 dst, const void* src, bool pred) {
    int sz = pred ? 16 : 0;
    asm volatile("cp.async.cg.shared.global [%0], [%1], 16, %2;\n"
                 :: "r"(dst), "l"(src), "r"(sz));
}
__device__ __forceinline__ void cp_commit() { asm volatile("cp.async.commit_group;\n"); }
__device__ __forceinline__ void cp_wait1()  { asm volatile("cp.async.wait_group 1;\n"); }
__device__ __forceinline__ void cp_wait0()  { asm volatile("cp.async.wait_group 0;\n"); }

__device__ __forceinline__ void ldsm_x4(unsigned* r, unsigned addr) {
    asm volatile("ldmatrix.sync.aligned.m8n8.x4.shared.b16 {%0,%1,%2,%3}, [%4];"
                 : "=r"(r[0]), "=r"(r[1]), "=r"(r[2]), "=r"(r[3]) : "r"(addr));
}

__device__ __forceinline__ void ldsm_x4_t(unsigned* r, unsigned addr) {
    asm volatile("ldmatrix.sync.aligned.m8n8.x4.trans.shared.b16 {%0,%1,%2,%3}, [%4];"
                 : "=r"(r[0]), "=r"(r[1]), "=r"(r[2]), "=r"(r[3]) : "r"(addr));
}

__device__ __forceinline__ void mma_f16(float* d, const unsigned* a, const unsigned* b) {
    asm volatile(
        "mma.sync.aligned.m16n8k16.row.col.f32.f16.f16.f32 "
        "{%0,%1,%2,%3}, {%4,%5,%6,%7}, {%8,%9}, {%0,%1,%2,%3};\n"
        : "+f"(d[0]), "+f"(d[1]), "+f"(d[2]), "+f"(d[3])
        : "r"(a[0]), "r"(a[1]), "r"(a[2]), "r"(a[3]), "r"(b[0]), "r"(b[1]));
}

// ---------------- conversions ----------------
// fp32 -> fp16, 8 elems/thread
__global__ void k_cvt16(const float* __restrict__ in, __half* __restrict__ outp, int n8) {
    int i = blockIdx.x * blockDim.x + threadIdx.x;
    if (i >= n8) return;
    float4 a = ((const float4*)in)[2 * i];
    float4 b = ((const float4*)in)[2 * i + 1];
    __half2 h0 = __floats2half2_rn(a.x, a.y);
    __half2 h1 = __floats2half2_rn(a.z, a.w);
    __half2 h2 = __floats2half2_rn(b.x, b.y);
    __half2 h3 = __floats2half2_rn(b.z, b.w);
    uint4 v;
    v.x = *(u32*)&h0; v.y = *(u32*)&h1; v.z = *(u32*)&h2; v.w = *(u32*)&h3;
    ((uint4*)outp)[i] = v;
}

// fp32 W -> fp16 hi/lo planes (same [K][N] layout), 8 elems/thread
__global__ void k_cvtw(const float* __restrict__ in, __half* __restrict__ hi,
                       __half* __restrict__ lo, int n8) {
    int i = blockIdx.x * blockDim.x + threadIdx.x;
    if (i >= n8) return;
    float4 a = ((const float4*)in)[2 * i];
    float4 b = ((const float4*)in)[2 * i + 1];
    float f[8] = {a.x, a.y, a.z, a.w, b.x, b.y, b.z, b.w};
    __half h[8], l[8];
#pragma unroll
    for (int j = 0; j < 8; j++) {
        h[j] = __float2half_rn(f[j]);
        l[j] = __float2half_rn(f[j] - __half2float(h[j]));
    }
    ((uint4*)hi)[i] = *(uint4*)h;
    ((uint4*)lo)[i] = *(uint4*)l;
}

// ---------------- CSR build ----------------
__global__ void k_hist(const int* __restrict__ rows) {
    int e = blockIdx.x * blockDim.x + threadIdx.x;
    if (e < Ee) atomicAdd(&g_cnt[rows[e]], 1);
}

// parallel scan: per-block exclusive scan + block sums
__global__ __launch_bounds__(512) void k_scan1() {
    __shared__ int sm[512];
    int b = blockIdx.x, t = threadIdx.x;
    int i = b * 512 + t;
    int v = (i < Nn) ? g_cnt[i] : 0;
    sm[t] = v;
    __syncthreads();
    for (int off = 1; off < 512; off <<= 1) {
        int add = (t >= off) ? sm[t - off] : 0;
        __syncthreads();
        sm[t] += add;
        __syncthreads();
    }
    if (i < Nn) g_rowptr[i] = sm[t] - v;
    if (t == 511) g_blksum[b] = sm[511];
}

__global__ __launch_bounds__(128) void k_scan2() {
    const int NB = (Nn + 511) / 512;  // 98
    __shared__ int sm[128];
    int t = threadIdx.x;
    int v = (t < NB) ? g_blksum[t] : 0;
    sm[t] = v;
    __syncthreads();
    for (int off = 1; off < 128; off <<= 1) {
        int add = (t >= off) ? sm[t - off] : 0;
        __syncthreads();
        sm[t] += add;
        __syncthreads();
    }
    if (t < NB) g_blksum[t] = sm[t] - v;
}

__global__ __launch_bounds__(512) void k_scan3() {
    int b = blockIdx.x;
    int i = b * 512 + threadIdx.x;
    if (i < Nn) {
        g_rowptr[i] += g_blksum[b];
        g_cnt[i] = 0;
    }
    if (i == 0) g_rowptr[Nn] = Ee;
}

__global__ void k_scatter(const int* __restrict__ rows,
                          const int* __restrict__ cols,
                          const float* __restrict__ vals) {
    int e = blockIdx.x * blockDim.x + threadIdx.x;
    if (e >= Ee) return;
    int r = rows[e];
    int pos = g_rowptr[r] + atomicAdd(&g_cnt[r], 1);
    g_ecol[pos] = cols[e];
    g_eval[pos] = vals[e];
}

// ---------------- 2-stage pipelined 2-pass fp16 tensor GEMM, fp16 output ----------------
// C = A_f16 @ (B_h + B_l). BM=128, BK=32, 256 threads, 8 warps (WM x WN).
template <int BN, int WM, int WN>
__device__ __forceinline__ void gemm_f16(const __half* __restrict__ Ag,
                                         const __half* __restrict__ Bhg,
                                         const __half* __restrict__ Blg,
                                         __half* __restrict__ C,
                                         int M, int K, int Nd) {
    constexpr int BM = 128, BK = 32;
    constexpr int AP = 40;           // A smem row stride: 80B, odd 16B units
    constexpr int BP = BN + 8;       // B smem row stride (odd 16B units)
    constexpr int MT = (BM / WM) / 16;
    constexpr int NT = (BN / WN) / 8;
    constexpr int ASTG = BM * AP;
    constexpr int BSTG = BK * BP;

    extern __shared__ u16 sm[];
    u16* As = sm;
    u16* Bh = As + 2 * ASTG;
    u16* Bl = Bh + 2 * BSTG;

    const int tid = threadIdx.x;
    const int lane = tid & 31;
    const int warp = tid >> 5;
    const int wm = warp / WN;
    const int wn = warp % WN;
    const int g = lane >> 2;
    const int t4 = lane & 3;
    const int rowBase = blockIdx.x * BM;
    const int colBase = blockIdx.y * BN;

    float acc[MT][NT][4];
#pragma unroll
    for (int mt = 0; mt < MT; mt++)
#pragma unroll
        for (int nt = 0; nt < NT; nt++)
#pragma unroll
            for (int i = 0; i < 4; i++) acc[mt][nt][i] = 0.0f;

    constexpr int ACH = BK / 8;                   // 4 chunks per A row
    constexpr int A_ITERS = BM * ACH / 256;       // 2
    constexpr int BCH = BN / 8;                   // chunks per B row per plane
    constexpr int B_ITERS = (BK * BCH + 255) / 256;

    auto issue = [&](int t, int stage) {
        int k0 = t * BK;
        unsigned aoff = stage * ASTG;
        unsigned boff = stage * BSTG;
#pragma unroll
        for (int it = 0; it < A_ITERS; it++) {
            int slot = tid + it * 256;
            int r = slot >> 2, ch = slot & 3;
            int gr = rowBase + r;
            bool p = gr < M;
            cpa16(smem_u32(&As[aoff + r * AP + ch * 8]),
                  Ag + (size_t)gr * K + k0 + ch * 8, p);
        }
#pragma unroll
        for (int it = 0; it < B_ITERS; it++) {
            int slot = tid + it * 256;
            if (slot < BK * BCH) {
                int r = slot / BCH, ch = slot % BCH;
                size_t go = (size_t)(k0 + r) * Nd + colBase + ch * 8;
                cpa16(smem_u32(&Bh[boff + r * BP + ch * 8]), Bhg + go, true);
                cpa16(smem_u32(&Bl[boff + r * BP + ch * 8]), Blg + go, true);
            }
        }
        cp_commit();
    };

    const int T = K / BK;
    issue(0, 0);

    for (int t = 0; t < T; t++) {
        int stage = t & 1;
        if (t + 1 < T) {
            issue(t + 1, stage ^ 1);
            cp_wait1();
        } else {
            cp_wait0();
        }
        __syncthreads();

        unsigned aoff = stage * ASTG;
        unsigned boff = stage * BSTG;
#pragma unroll
        for (int ks = 0; ks < 2; ks++) {
            const int kk = ks * 16;
            unsigned b_h[NT][2], b_l[NT][2];
#pragma unroll
            for (int p = 0; p < NT / 2; p++) {
                int k = kk + (lane & 15);
                int n = wn * (BN / WN) + p * 16 + (lane >> 4) * 8;
                unsigned th[4], tl[4];
                ldsm_x4_t(th, smem_u32(&Bh[boff + k * BP + n]));
                ldsm_x4_t(tl, smem_u32(&Bl[boff + k * BP + n]));
                b_h[2 * p][0] = th[0]; b_h[2 * p][1] = th[1];
                b_h[2 * p + 1][0] = th[2]; b_h[2 * p + 1][1] = th[3];
                b_l[2 * p][0] = tl[0]; b_l[2 * p][1] = tl[1];
                b_l[2 * p + 1][0] = tl[2]; b_l[2 * p + 1][1] = tl[3];
            }
#pragma unroll
            for (int mt = 0; mt < MT; mt++) {
                unsigned a[4];
                int r = wm * (BM / WM) + mt * 16 + (lane & 15);
                int c = kk + (lane >> 4) * 8;
                ldsm_x4(a, smem_u32(&As[aoff + r * AP + c]));
#pragma unroll
                for (int nt = 0; nt < NT; nt++) {
                    mma_f16(acc[mt][nt], a, b_h[nt]);
                    mma_f16(acc[mt][nt], a, b_l[nt]);
                }
            }
        }
        __syncthreads();
    }

    // epilogue: fp16 output
#pragma unroll
    for (int mt = 0; mt < MT; mt++) {
        int r0 = rowBase + wm * (BM / WM) + mt * 16 + g;
#pragma unroll
        for (int nt = 0; nt < NT; nt++) {
            int cn = colBase + wn * (BN / WN) + nt * 8 + t4 * 2;
            if (r0 < M)
                *(__half2*)&C[(size_t)r0 * Nd + cn] =
                    __floats2half2_rn(acc[mt][nt][0], acc[mt][nt][1]);
            if (r0 + 8 < M)
                *(__half2*)&C[(size_t)(r0 + 8) * Nd + cn] =
                    __floats2half2_rn(acc[mt][nt][2], acc[mt][nt][3]);
        }
    }
}

__global__ __launch_bounds__(256, 2) void k_gemm1() {
    gemm_f16<128, 2, 4>(g_x16, g_w1h, g_w1l, g_H1, Nn, IN_DIM, HIDD);
}

__global__ __launch_bounds__(256, 2) void k_gemm2() {
    gemm_f16<64, 4, 2>(g_s116, g_w2h, g_w2l, g_H2, Nn, HIDD, OUTD);
}

// ---------------- SpMM 1: S1 = relu(csr_spmm(H1)+b1) -> fp16 ----------------
__global__ __launch_bounds__(128) void k_spmm1(const float* __restrict__ b1) {
    int row = blockIdx.x;
    int d2 = threadIdx.x;            // half2 column 0..127
    const __half2* H = (const __half2*)g_H1;
    int s = g_rowptr[row];
    int e = g_rowptr[row + 1];
    float ax = 0.0f, ay = 0.0f;
    int j = s;
    for (; j + 4 <= e; j += 4) {
        int   c0 = g_ecol[j + 0], c1 = g_ecol[j + 1], c2 = g_ecol[j + 2], c3 = g_ecol[j + 3];
        float v0 = g_eval[j + 0], v1 = g_eval[j + 1], v2 = g_eval[j + 2], v3 = g_eval[j + 3];
        float2 h0 = __half22float2(H[(size_t)c0 * 128 + d2]);
        float2 h1 = __half22float2(H[(size_t)c1 * 128 + d2]);
        float2 h2 = __half22float2(H[(size_t)c2 * 128 + d2]);
        float2 h3 = __half22float2(H[(size_t)c3 * 128 + d2]);
        ax = fmaf(v0, h0.x, ax); ay = fmaf(v0, h0.y, ay);
        ax = fmaf(v1, h1.x, ax); ay = fmaf(v1, h1.y, ay);
        ax = fmaf(v2, h2.x, ax); ay = fmaf(v2, h2.y, ay);
        ax = fmaf(v3, h3.x, ax); ay = fmaf(v3, h3.y, ay);
    }
    for (; j < e; j++) {
        float v = g_eval[j];
        float2 h = __half22float2(H[(size_t)g_ecol[j] * 128 + d2]);
        ax = fmaf(v, h.x, ax); ay = fmaf(v, h.y, ay);
    }
    float2 bb = ((const float2*)b1)[d2];
    float ox = fmaxf(ax + bb.x, 0.0f);
    float oy = fmaxf(ay + bb.y, 0.0f);
    ((__half2*)g_s116)[(size_t)row * 128 + d2] = __floats2half2_rn(ox, oy);
}

// ---------------- SpMM 2: out = csr_spmm(H2) + b2, 8 rows/block ----------------
__global__ __launch_bounds__(256) void k_spmm2(const float* __restrict__ b2,
                                               float* __restrict__ out) {
    int row = blockIdx.x * 8 + (threadIdx.x >> 5);
    int d2 = threadIdx.x & 31;       // half2 column 0..31
    if (row >= Nn) return;
    const __half2* H = (const __half2*)g_H2;
    int s = g_rowptr[row];
    int e = g_rowptr[row + 1];
    float ax = 0.0f, ay = 0.0f;
    int j = s;
    for (; j + 4 <= e; j += 4) {
        int   c0 = g_ecol[j + 0], c1 = g_ecol[j + 1], c2 = g_ecol[j + 2], c3 = g_ecol[j + 3];
        float v0 = g_eval[j + 0], v1 = g_eval[j + 1], v2 = g_eval[j + 2], v3 = g_eval[j + 3];
        float2 h0 = __half22float2(H[(size_t)c0 * 32 + d2]);
        float2 h1 = __half22float2(H[(size_t)c1 * 32 + d2]);
        float2 h2 = __half22float2(H[(size_t)c2 * 32 + d2]);
        float2 h3 = __half22float2(H[(size_t)c3 * 32 + d2]);
        ax = fmaf(v0, h0.x, ax); ay = fmaf(v0, h0.y, ay);
        ax = fmaf(v1, h1.x, ax); ay = fmaf(v1, h1.y, ay);
        ax = fmaf(v2, h2.x, ax); ay = fmaf(v2, h2.y, ay);
        ax = fmaf(v3, h3.x, ax); ay = fmaf(v3, h3.y, ay);
    }
    for (; j < e; j++) {
        float v = g_eval[j];
        float2 h = __half22float2(H[(size_t)g_ecol[j] * 32 + d2]);
        ax = fmaf(v, h.x, ax); ay = fmaf(v, h.y, ay);
    }
    float2 bb = ((const float2*)b2)[d2];
    ((float2*)out)[(size_t)row * 32 + d2] = make_float2(ax + bb.x, ay + bb.y);
}

// ---------------- entry point ----------------
extern "C" void kernel_launch(void* const* d_in, const int* in_sizes, int n_in,
                              void* d_out, int out_size) {
    const float* x    = (const float*)d_in[0];
    const int*   rows = (const int*)  d_in[1];
    const int*   cols = (const int*)  d_in[2];
    const float* vals = (const float*)d_in[3];
    const float* W1   = (const float*)d_in[4];
    const float* b1   = (const float*)d_in[5];
    const float* W2   = (const float*)d_in[6];
    const float* b2   = (const float*)d_in[7];
    float* out = (float*)d_out;

    // dynamic smem (u16 counts -> bytes)
    const int smem1 = (2 * 128 * 40 + 2 * 2 * 32 * (128 + 8)) * 2;  // 55296
    const int smem2 = (2 * 128 * 40 + 2 * 2 * 32 * (64 + 8)) * 2;   // 38912
    cudaFuncSetAttribute(k_gemm1, cudaFuncAttributeMaxDynamicSharedMemorySize, smem1);
    cudaFuncSetAttribute(k_gemm2, cudaFuncAttributeMaxDynamicSharedMemorySize, smem2);

    __half *x16, *w1h, *w1l, *w2h, *w2l;
    cudaGetSymbolAddress((void**)&x16, g_x16);
    cudaGetSymbolAddress((void**)&w1h, g_w1h);
    cudaGetSymbolAddress((void**)&w1l, g_w1l);
    cudaGetSymbolAddress((void**)&w2h, g_w2h);
    cudaGetSymbolAddress((void**)&w2l, g_w2l);
    int* cnt;
    cudaGetSymbolAddress((void**)&cnt, g_cnt);

    // conversions first; gemm1 stays the 4th kernel launch (ncu window)
    k_cvt16<<<(Nn * IN_DIM / 8 + 255) / 256, 256>>>(x, x16, Nn * IN_DIM / 8);
    k_cvtw<<<(IN_DIM * HIDD / 8 + 255) / 256, 256>>>(W1, w1h, w1l, IN_DIM * HIDD / 8);
    k_cvtw<<<(HIDD * OUTD / 8 + 255) / 256, 256>>>(W2, w2h, w2l, HIDD * OUTD / 8);

    // layer 1 GEMM
    k_gemm1<<<dim3((Nn + 127) / 128, HIDD / 128), 256, smem1>>>();

    // CSR build (independent of gemm1; needed by spmm1)
    cudaMemsetAsync(cnt, 0, Nn * sizeof(int));
    k_hist<<<(Ee + 255) / 256, 256>>>(rows);
    k_scan1<<<(Nn + 511) / 512, 512>>>();
    k_scan2<<<1, 128>>>();
    k_scan3<<<(Nn + 511) / 512, 512>>>();
    k_scatter<<<(Ee + 255) / 256, 256>>>(rows, cols, vals);

    // aggregate layer 1
    k_spmm1<<<Nn, 128>>>(b1);

    // layer 2
    k_gemm2<<<dim3((Nn + 127) / 128, 1), 256, smem2>>>();
    k_spmm2<<<(Nn + 7) / 8, 256>>>(b2, out);
}

// round 9
// speedup vs baseline: 3.5142x; 1.1989x over previous
#include <cuda_runtime.h>
#include <cuda_fp16.h>

#define Nn      50000
#define Ee      800000
#define IN_DIM  512
#define HIDD    256
#define OUTD    64

typedef unsigned short u16;
typedef unsigned int   u32;

// ---------------- scratch (device globals; no allocs allowed) ----------------
__device__ __half    g_H1[(size_t)Nn * HIDD];        // x @ W1 (fp16)
__device__ __half    g_H2[(size_t)Nn * OUTD];        // S1 @ W2 (fp16)
__device__ __half    g_x16[(size_t)Nn * IN_DIM];     // x as fp16
__device__ __half    g_s116[(size_t)Nn * HIDD];      // S1 as fp16
__device__ __half    g_w116[IN_DIM * HIDD];          // W1 fp16 [K][N]
__device__ __half    g_w216[HIDD * OUTD];            // W2 fp16
__device__ int       g_cnt[Nn];
__device__ int       g_rowptr[Nn + 1];
__device__ int       g_blksum[128];
__device__ uint2     g_edge[Ee];                      // (col, val bits)

// ---------------- helpers ----------------
__device__ __forceinline__ u32 smem_u32(const void* p) {
    return (u32)__cvta_generic_to_shared(p);
}

__device__ __forceinline__ void cpa16(u32 dst, const void* src, bool pred) {
    int sz = pred ? 16 : 0;
    asm volatile("cp.async.cg.shared.global [%0], [%1], 16, %2;\n"
                 :: "r"(dst), "l"(src), "r"(sz));
}
__device__ __forceinline__ void cp_commit() { asm volatile("cp.async.commit_group;\n"); }
__device__ __forceinline__ void cp_wait2()  { asm volatile("cp.async.wait_group 2;\n"); }
__device__ __forceinline__ void cp_wait1()  { asm volatile("cp.async.wait_group 1;\n"); }
__device__ __forceinline__ void cp_wait0()  { asm volatile("cp.async.wait_group 0;\n"); }

__device__ __forceinline__ void ldsm_x4(unsigned* r, unsigned addr) {
    asm volatile("ldmatrix.sync.aligned.m8n8.x4.shared.b16 {%0,%1,%2,%3}, [%4];"
                 : "=r"(r[0]), "=r"(r[1]), "=r"(r[2]), "=r"(r[3]) : "r"(addr));
}

__device__ __forceinline__ void ldsm_x4_t(unsigned* r, unsigned addr) {
    asm volatile("ldmatrix.sync.aligned.m8n8.x4.trans.shared.b16 {%0,%1,%2,%3}, [%4];"
                 : "=r"(r[0]), "=r"(r[1]), "=r"(r[2]), "=r"(r[3]) : "r"(addr));
}

__device__ __forceinline__ void mma_f16(float* d, const unsigned* a, const unsigned* b) {
    asm volatile(
        "mma.sync.aligned.m16n8k16.row.col.f32.f16.f16.f32 "
        "{%0,%1,%2,%3}, {%4,%5,%6,%7}, {%8,%9}, {%0,%1,%2,%3};\n"
        : "+f"(d[0]), "+f"(d[1]), "+f"(d[2]), "+f"(d[3])
        : "r"(a[0]), "r"(a[1]), "r"(a[2]), "r"(a[3]), "r"(b[0]), "r"(b[1]));
}

// ---------------- conversions ----------------
__global__ void k_cvt16(const float* __restrict__ in, __half* __restrict__ outp, int n8) {
    int i = blockIdx.x * blockDim.x + threadIdx.x;
    if (i >= n8) return;
    float4 a = ((const float4*)in)[2 * i];
    float4 b = ((const float4*)in)[2 * i + 1];
    __half2 h0 = __floats2half2_rn(a.x, a.y);
    __half2 h1 = __floats2half2_rn(a.z, a.w);
    __half2 h2 = __floats2half2_rn(b.x, b.y);
    __half2 h3 = __floats2half2_rn(b.z, b.w);
    uint4 v;
    v.x = *(u32*)&h0; v.y = *(u32*)&h1; v.z = *(u32*)&h2; v.w = *(u32*)&h3;
    ((uint4*)outp)[i] = v;
}

// ---------------- CSR build ----------------
__global__ void k_hist(const int* __restrict__ rows) {
    int e = blockIdx.x * blockDim.x + threadIdx.x;
    if (e < Ee) atomicAdd(&g_cnt[rows[e]], 1);
}

__global__ __launch_bounds__(512) void k_scan1() {
    __shared__ int sm[512];
    int b = blockIdx.x, t = threadIdx.x;
    int i = b * 512 + t;
    int v = (i < Nn) ? g_cnt[i] : 0;
    sm[t] = v;
    __syncthreads();
    for (int off = 1; off < 512; off <<= 1) {
        int add = (t >= off) ? sm[t - off] : 0;
        __syncthreads();
        sm[t] += add;
        __syncthreads();
    }
    if (i < Nn) g_rowptr[i] = sm[t] - v;
    if (t == 511) g_blksum[b] = sm[511];
}

__global__ __launch_bounds__(128) void k_scan2() {
    const int NB = (Nn + 511) / 512;  // 98
    __shared__ int sm[128];
    int t = threadIdx.x;
    int v = (t < NB) ? g_blksum[t] : 0;
    sm[t] = v;
    __syncthreads();
    for (int off = 1; off < 128; off <<= 1) {
        int add = (t >= off) ? sm[t - off] : 0;
        __syncthreads();
        sm[t] += add;
        __syncthreads();
    }
    if (t < NB) g_blksum[t] = sm[t] - v;
}

__global__ __launch_bounds__(512) void k_scan3() {
    int b = blockIdx.x;
    int i = b * 512 + threadIdx.x;
    if (i < Nn) {
        g_rowptr[i] += g_blksum[b];
        g_cnt[i] = 0;
    }
    if (i == 0) g_rowptr[Nn] = Ee;
}

__global__ void k_scatter(const int* __restrict__ rows,
                          const int* __restrict__ cols,
                          const float* __restrict__ vals) {
    int e = blockIdx.x * blockDim.x + threadIdx.x;
    if (e >= Ee) return;
    int r = rows[e];
    int pos = g_rowptr[r] + atomicAdd(&g_cnt[r], 1);
    g_edge[pos] = make_uint2((u32)cols[e], __float_as_uint(vals[e]));
}

// ---------------- 3-stage pipelined fp16 tensor GEMM, fp16 output ----------------
// C = A @ B, all fp16 in, fp32 acc, fp16 out. BM=128, BK=32, 256 threads (WM x WN warps).
template <int BN, int WM, int WN>
__device__ __forceinline__ void gemm_f16(const __half* __restrict__ Ag,
                                         const __half* __restrict__ Bg,
                                         __half* __restrict__ C,
                                         int M, int K, int Nd) {
    constexpr int BM = 128, BK = 32;
    constexpr int AP = 40;           // A smem row stride: 80B, odd 16B units
    constexpr int BP = BN + 8;       // B smem row stride (odd 16B units)
    constexpr int MT = (BM / WM) / 16;
    constexpr int NT = (BN / WN) / 8;
    constexpr int NSTG = 3;
    constexpr int ASTG = BM * AP;
    constexpr int BSTG = BK * BP;

    extern __shared__ u16 sm[];
    u16* As = sm;
    u16* Bs = As + NSTG * ASTG;

    const int tid = threadIdx.x;
    const int lane = tid & 31;
    const int warp = tid >> 5;
    const int wm = warp / WN;
    const int wn = warp % WN;
    const int g = lane >> 2;
    const int t4 = lane & 3;
    const int rowBase = blockIdx.x * BM;
    const int colBase = blockIdx.y * BN;

    float acc[MT][NT][4];
#pragma unroll
    for (int mt = 0; mt < MT; mt++)
#pragma unroll
        for (int nt = 0; nt < NT; nt++)
#pragma unroll
            for (int i = 0; i < 4; i++) acc[mt][nt][i] = 0.0f;

    constexpr int ACH = BK / 8;                   // 4 chunks per A row
    constexpr int A_ITERS = BM * ACH / 256;       // 2
    constexpr int BCH = BN / 8;                   // chunks per B row
    constexpr int B_ITERS = (BK * BCH + 255) / 256;

    auto issue = [&](int t, int stage) {
        int k0 = t * BK;
        unsigned aoff = stage * ASTG;
        unsigned boff = stage * BSTG;
#pragma unroll
        for (int it = 0; it < A_ITERS; it++) {
            int slot = tid + it * 256;
            int r = slot >> 2, ch = slot & 3;
            int gr = rowBase + r;
            bool p = gr < M;
            cpa16(smem_u32(&As[aoff + r * AP + ch * 8]),
                  Ag + (size_t)gr * K + k0 + ch * 8, p);
        }
#pragma unroll
        for (int it = 0; it < B_ITERS; it++) {
            int slot = tid + it * 256;
            if (slot < BK * BCH) {
                int r = slot / BCH, ch = slot % BCH;
                cpa16(smem_u32(&Bs[boff + r * BP + ch * 8]),
                      Bg + (size_t)(k0 + r) * Nd + colBase + ch * 8, true);
            }
        }
        cp_commit();
    };

    const int T = K / BK;
    issue(0, 0);
    if (T > 1) issue(1, 1);

    for (int t = 0; t < T; t++) {
        if (t + 2 < T) {
            issue(t + 2, (t + 2) % NSTG);
            cp_wait2();
        } else if (t + 1 < T) {
            cp_wait1();
        } else {
            cp_wait0();
        }
        __syncthreads();

        int stage = t % NSTG;
        unsigned aoff = stage * ASTG;
        unsigned boff = stage * BSTG;
#pragma unroll
        for (int ks = 0; ks < 2; ks++) {
            const int kk = ks * 16;
            unsigned bf[NT][2];
#pragma unroll
            for (int p = 0; p < NT / 2; p++) {
                int k = kk + (lane & 15);
                int n = wn * (BN / WN) + p * 16 + (lane >> 4) * 8;
                unsigned tb[4];
                ldsm_x4_t(tb, smem_u32(&Bs[boff + k * BP + n]));
                bf[2 * p][0] = tb[0]; bf[2 * p][1] = tb[1];
                bf[2 * p + 1][0] = tb[2]; bf[2 * p + 1][1] = tb[3];
            }
#pragma unroll
            for (int mt = 0; mt < MT; mt++) {
                unsigned a[4];
                int r = wm * (BM / WM) + mt * 16 + (lane & 15);
                int c = kk + (lane >> 4) * 8;
                ldsm_x4(a, smem_u32(&As[aoff + r * AP + c]));
#pragma unroll
                for (int nt = 0; nt < NT; nt++)
                    mma_f16(acc[mt][nt], a, bf[nt]);
            }
        }
        __syncthreads();
    }

    // epilogue: fp16 output
#pragma unroll
    for (int mt = 0; mt < MT; mt++) {
        int r0 = rowBase + wm * (BM / WM) + mt * 16 + g;
#pragma unroll
        for (int nt = 0; nt < NT; nt++) {
            int cn = colBase + wn * (BN / WN) + nt * 8 + t4 * 2;
            if (r0 < M)
                *(__half2*)&C[(size_t)r0 * Nd + cn] =
                    __floats2half2_rn(acc[mt][nt][0], acc[mt][nt][1]);
            if (r0 + 8 < M)
                *(__half2*)&C[(size_t)(r0 + 8) * Nd + cn] =
                    __floats2half2_rn(acc[mt][nt][2], acc[mt][nt][3]);
        }
    }
}

__global__ __launch_bounds__(256, 2) void k_gemm1() {
    gemm_f16<128, 2, 4>(g_x16, g_w116, g_H1, Nn, IN_DIM, HIDD);
}

__global__ __launch_bounds__(256, 2) void k_gemm2() {
    gemm_f16<64, 4, 2>(g_s116, g_w216, g_H2, Nn, HIDD, OUTD);
}

// ---------------- SpMM 1: S1 = relu(csr_spmm(H1)+b1) -> fp16 ----------------
__global__ __launch_bounds__(128) void k_spmm1(const float* __restrict__ b1) {
    int row = blockIdx.x;
    int d2 = threadIdx.x;            // half2 column 0..127
    const __half2* H = (const __half2*)g_H1;
    int s = g_rowptr[row];
    int e = g_rowptr[row + 1];
    float ax = 0.0f, ay = 0.0f;
    int j = s;
    for (; j + 4 <= e; j += 4) {
        uint2 e0 = g_edge[j + 0], e1 = g_edge[j + 1], e2 = g_edge[j + 2], e3 = g_edge[j + 3];
        float v0 = __uint_as_float(e0.y), v1 = __uint_as_float(e1.y);
        float v2 = __uint_as_float(e2.y), v3 = __uint_as_float(e3.y);
        float2 h0 = __half22float2(H[(size_t)e0.x * 128 + d2]);
        float2 h1 = __half22float2(H[(size_t)e1.x * 128 + d2]);
        float2 h2 = __half22float2(H[(size_t)e2.x * 128 + d2]);
        float2 h3 = __half22float2(H[(size_t)e3.x * 128 + d2]);
        ax = fmaf(v0, h0.x, ax); ay = fmaf(v0, h0.y, ay);
        ax = fmaf(v1, h1.x, ax); ay = fmaf(v1, h1.y, ay);
        ax = fmaf(v2, h2.x, ax); ay = fmaf(v2, h2.y, ay);
        ax = fmaf(v3, h3.x, ax); ay = fmaf(v3, h3.y, ay);
    }
    for (; j < e; j++) {
        uint2 ee = g_edge[j];
        float v = __uint_as_float(ee.y);
        float2 h = __half22float2(H[(size_t)ee.x * 128 + d2]);
        ax = fmaf(v, h.x, ax); ay = fmaf(v, h.y, ay);
    }
    float2 bb = ((const float2*)b1)[d2];
    float ox = fmaxf(ax + bb.x, 0.0f);
    float oy = fmaxf(ay + bb.y, 0.0f);
    ((__half2*)g_s116)[(size_t)row * 128 + d2] = __floats2half2_rn(ox, oy);
}

// ---------------- SpMM 2: out = csr_spmm(H2) + b2, 8 rows/block ----------------
__global__ __launch_bounds__(256) void k_spmm2(const float* __restrict__ b2,
                                               float* __restrict__ out) {
    int row = blockIdx.x * 8 + (threadIdx.x >> 5);
    int d2 = threadIdx.x & 31;       // half2 column 0..31
    if (row >= Nn) return;
    const __half2* H = (const __half2*)g_H2;
    int s = g_rowptr[row];
    int e = g_rowptr[row + 1];
    float ax = 0.0f, ay = 0.0f;
    int j = s;
    for (; j + 4 <= e; j += 4) {
        uint2 e0 = g_edge[j + 0], e1 = g_edge[j + 1], e2 = g_edge[j + 2], e3 = g_edge[j + 3];
        float v0 = __uint_as_float(e0.y), v1 = __uint_as_float(e1.y);
        float v2 = __uint_as_float(e2.y), v3 = __uint_as_float(e3.y);
        float2 h0 = __half22float2(H[(size_t)e0.x * 32 + d2]);
        float2 h1 = __half22float2(H[(size_t)e1.x * 32 + d2]);
        float2 h2 = __half22float2(H[(size_t)e2.x * 32 + d2]);
        float2 h3 = __half22float2(H[(size_t)e3.x * 32 + d2]);
        ax = fmaf(v0, h0.x, ax); ay = fmaf(v0, h0.y, ay);
        ax = fmaf(v1, h1.x, ax); ay = fmaf(v1, h1.y, ay);
        ax = fmaf(v2, h2.x, ax); ay = fmaf(v2, h2.y, ay);
        ax = fmaf(v3, h3.x, ax); ay = fmaf(v3, h3.y, ay);
    }
    for (; j < e; j++) {
        uint2 ee = g_edge[j];
        float v = __uint_as_float(ee.y);
        float2 h = __half22float2(H[(size_t)ee.x * 32 + d2]);
        ax = fmaf(v, h.x, ax); ay = fmaf(v, h.y, ay);
    }
    float2 bb = ((const float2*)b2)[d2];
    ((float2*)out)[(size_t)row * 32 + d2] = make_float2(ax + bb.x, ay + bb.y);
}

// ---------------- entry point ----------------
extern "C" void kernel_launch(void* const* d_in, const int* in_sizes, int n_in,
                              void* d_out, int out_size) {
    const float* x    = (const float*)d_in[0];
    const int*   rows = (const int*)  d_in[1];
    const int*   cols = (const int*)  d_in[2];
    const float* vals = (const float*)d_in[3];
    const float* W1   = (const float*)d_in[4];
    const float* b1   = (const float*)d_in[5];
    const float* W2   = (const float*)d_in[6];
    const float* b2   = (const float*)d_in[7];
    float* out = (float*)d_out;

    // dynamic smem (u16 counts -> bytes): 3 stages, single B plane
    const int smem1 = (3 * 128 * 40 + 3 * 32 * (128 + 8)) * 2;  // 56832
    const int smem2 = (3 * 128 * 40 + 3 * 32 * (64 + 8)) * 2;   // 44544
    cudaFuncSetAttribute(k_gemm1, cudaFuncAttributeMaxDynamicSharedMemorySize, smem1);
    cudaFuncSetAttribute(k_gemm2, cudaFuncAttributeMaxDynamicSharedMemorySize, smem2);

    __half *x16, *w116, *w216;
    cudaGetSymbolAddress((void**)&x16,  g_x16);
    cudaGetSymbolAddress((void**)&w116, g_w116);
    cudaGetSymbolAddress((void**)&w216, g_w216);
    int* cnt;
    cudaGetSymbolAddress((void**)&cnt, g_cnt);

    // conversions first; gemm1 stays the 4th kernel launch (ncu window)
    k_cvt16<<<(Nn * IN_DIM / 8 + 255) / 256, 256>>>(x, x16, Nn * IN_DIM / 8);
    k_cvt16<<<(IN_DIM * HIDD / 8 + 255) / 256, 256>>>(W1, w116, IN_DIM * HIDD / 8);
    k_cvt16<<<(HIDD * OUTD / 8 + 255) / 256, 256>>>(W2, w216, HIDD * OUTD / 8);

    // layer 1 GEMM
    k_gemm1<<<dim3((Nn + 127) / 128, HIDD / 128), 256, smem1>>>();

    // CSR build (independent of gemm1; needed by spmm1)
    cudaMemsetAsync(cnt, 0, Nn * sizeof(int));
    k_hist<<<(Ee + 255) / 256, 256>>>(rows);
    k_scan1<<<(Nn + 511) / 512, 512>>>();
    k_scan2<<<1, 128>>>();
    k_scan3<<<(Nn + 511) / 512, 512>>>();
    k_scatter<<<(Ee + 255) / 256, 256>>>(rows, cols, vals);

    // aggregate layer 1
    k_spmm1<<<Nn, 128>>>(b1);

    // layer 2
    k_gemm2<<<dim3((Nn + 127) / 128, 1), 256, smem2>>>();
    k_spmm2<<<(Nn + 7) / 8, 256>>>(b2, out);
}

// round 10
// speedup vs baseline: 3.5846x; 1.0200x over previous
#include <cuda_runtime.h>
#include <cuda_fp16.h>

#define Nn      50000
#define Ee      800000
#define IN_DIM  512
#define HIDD    256
#define OUTD    64

typedef unsigned short u16;
typedef unsigned int   u32;

// ---------------- scratch (device globals; no allocs allowed) ----------------
__device__ __half    g_H1[(size_t)Nn * HIDD];        // x @ W1 (fp16)
__device__ __half    g_H2[(size_t)Nn * OUTD];        // S1 @ W2 (fp16)
__device__ __half    g_x16[(size_t)Nn * IN_DIM];     // x as fp16
__device__ __half    g_s116[(size_t)Nn * HIDD];      // S1 as fp16
__device__ __half    g_w116[IN_DIM * HIDD];          // W1 fp16 [K][N]
__device__ __half    g_w216[HIDD * OUTD];            // W2 fp16
__device__ int       g_cnt[Nn];
__device__ int       g_rowptr[Nn + 1];
__device__ int       g_blksum[128];
__device__ uint2     g_edge[Ee];                      // (col, val bits)

// ---------------- helpers ----------------
__device__ __forceinline__ u32 smem_u32(const void* p) {
    return (u32)__cvta_generic_to_shared(p);
}

__device__ __forceinline__ void cpa16(u32 dst, const void* src, bool pred) {
    int sz = pred ? 16 : 0;
    asm volatile("cp.async.cg.shared.global [%0], [%1], 16, %2;\n"
                 :: "r"(dst), "l"(src), "r"(sz));
}
__device__ __forceinline__ void cp_commit() { asm volatile("cp.async.commit_group;\n"); }
__device__ __forceinline__ void cp_wait2()  { asm volatile("cp.async.wait_group 2;\n"); }
__device__ __forceinline__ void cp_wait1()  { asm volatile("cp.async.wait_group 1;\n"); }
__device__ __forceinline__ void cp_wait0()  { asm volatile("cp.async.wait_group 0;\n"); }

__device__ __forceinline__ void ldsm_x4(unsigned* r, unsigned addr) {
    asm volatile("ldmatrix.sync.aligned.m8n8.x4.shared.b16 {%0,%1,%2,%3}, [%4];"
                 : "=r"(r[0]), "=r"(r[1]), "=r"(r[2]), "=r"(r[3]) : "r"(addr));
}

__device__ __forceinline__ void ldsm_x4_t(unsigned* r, unsigned addr) {
    asm volatile("ldmatrix.sync.aligned.m8n8.x4.trans.shared.b16 {%0,%1,%2,%3}, [%4];"
                 : "=r"(r[0]), "=r"(r[1]), "=r"(r[2]), "=r"(r[3]) : "r"(addr));
}

__device__ __forceinline__ void mma_f16(float* d, const unsigned* a, const unsigned* b) {
    asm volatile(
        "mma.sync.aligned.m16n8k16.row.col.f32.f16.f16.f32 "
        "{%0,%1,%2,%3}, {%4,%5,%6,%7}, {%8,%9}, {%0,%1,%2,%3};\n"
        : "+f"(d[0]), "+f"(d[1]), "+f"(d[2]), "+f"(d[3])
        : "r"(a[0]), "r"(a[1]), "r"(a[2]), "r"(a[3]), "r"(b[0]), "r"(b[1]));
}

// ---------------- conversions ----------------
__global__ void k_cvt16(const float* __restrict__ in, __half* __restrict__ outp, int n8) {
    int i = blockIdx.x * blockDim.x + threadIdx.x;
    if (i >= n8) return;
    float4 a = ((const float4*)in)[2 * i];
    float4 b = ((const float4*)in)[2 * i + 1];
    __half2 h0 = __floats2half2_rn(a.x, a.y);
    __half2 h1 = __floats2half2_rn(a.z, a.w);
    __half2 h2 = __floats2half2_rn(b.x, b.y);
    __half2 h3 = __floats2half2_rn(b.z, b.w);
    uint4 v;
    v.x = *(u32*)&h0; v.y = *(u32*)&h1; v.z = *(u32*)&h2; v.w = *(u32*)&h3;
    ((uint4*)outp)[i] = v;
}

// ---------------- CSR build ----------------
__global__ void k_hist(const int* __restrict__ rows) {
    int e = blockIdx.x * blockDim.x + threadIdx.x;
    if (e < Ee) atomicAdd(&g_cnt[rows[e]], 1);
}

__global__ __launch_bounds__(512) void k_scan1() {
    __shared__ int sm[512];
    int b = blockIdx.x, t = threadIdx.x;
    int i = b * 512 + t;
    int v = (i < Nn) ? g_cnt[i] : 0;
    sm[t] = v;
    __syncthreads();
    for (int off = 1; off < 512; off <<= 1) {
        int add = (t >= off) ? sm[t - off] : 0;
        __syncthreads();
        sm[t] += add;
        __syncthreads();
    }
    if (i < Nn) g_rowptr[i] = sm[t] - v;
    if (t == 511) g_blksum[b] = sm[511];
}

__global__ __launch_bounds__(128) void k_scan2() {
    const int NB = (Nn + 511) / 512;  // 98
    __shared__ int sm[128];
    int t = threadIdx.x;
    int v = (t < NB) ? g_blksum[t] : 0;
    sm[t] = v;
    __syncthreads();
    for (int off = 1; off < 128; off <<= 1) {
        int add = (t >= off) ? sm[t - off] : 0;
        __syncthreads();
        sm[t] += add;
        __syncthreads();
    }
    if (t < NB) g_blksum[t] = sm[t] - v;
}

__global__ __launch_bounds__(512) void k_scan3() {
    int b = blockIdx.x;
    int i = b * 512 + threadIdx.x;
    if (i < Nn) {
        g_rowptr[i] += g_blksum[b];
        g_cnt[i] = 0;
    }
    if (i == 0) g_rowptr[Nn] = Ee;
}

__global__ void k_scatter(const int* __restrict__ rows,
                          const int* __restrict__ cols,
                          const float* __restrict__ vals) {
    int e = blockIdx.x * blockDim.x + threadIdx.x;
    if (e >= Ee) return;
    int r = rows[e];
    int pos = g_rowptr[r] + atomicAdd(&g_cnt[r], 1);
    g_edge[pos] = make_uint2((u32)cols[e], __float_as_uint(vals[e]));
}

// ---------------- 3-stage pipelined fp16 tensor GEMM, fp16 output ----------------
template <int BN, int WM, int WN>
__device__ __forceinline__ void gemm_f16(const __half* __restrict__ Ag,
                                         const __half* __restrict__ Bg,
                                         __half* __restrict__ C,
                                         int M, int K, int Nd) {
    constexpr int BM = 128, BK = 32;
    constexpr int AP = 40;           // A smem row stride: 80B, odd 16B units
    constexpr int BP = BN + 8;       // B smem row stride (odd 16B units)
    constexpr int MT = (BM / WM) / 16;
    constexpr int NT = (BN / WN) / 8;
    constexpr int NSTG = 3;
    constexpr int ASTG = BM * AP;
    constexpr int BSTG = BK * BP;

    extern __shared__ u16 sm[];
    u16* As = sm;
    u16* Bs = As + NSTG * ASTG;

    const int tid = threadIdx.x;
    const int lane = tid & 31;
    const int warp = tid >> 5;
    const int wm = warp / WN;
    const int wn = warp % WN;
    const int g = lane >> 2;
    const int t4 = lane & 3;
    const int rowBase = blockIdx.x * BM;
    const int colBase = blockIdx.y * BN;

    float acc[MT][NT][4];
#pragma unroll
    for (int mt = 0; mt < MT; mt++)
#pragma unroll
        for (int nt = 0; nt < NT; nt++)
#pragma unroll
            for (int i = 0; i < 4; i++) acc[mt][nt][i] = 0.0f;

    constexpr int ACH = BK / 8;
    constexpr int A_ITERS = BM * ACH / 256;   // 2
    constexpr int BCH = BN / 8;
    constexpr int B_ITERS = (BK * BCH + 255) / 256;

    auto issue = [&](int t, int stage) {
        int k0 = t * BK;
        unsigned aoff = stage * ASTG;
        unsigned boff = stage * BSTG;
#pragma unroll
        for (int it = 0; it < A_ITERS; it++) {
            int slot = tid + it * 256;
            int r = slot >> 2, ch = slot & 3;
            int gr = rowBase + r;
            bool p = gr < M;
            cpa16(smem_u32(&As[aoff + r * AP + ch * 8]),
                  Ag + (size_t)gr * K + k0 + ch * 8, p);
        }
#pragma unroll
        for (int it = 0; it < B_ITERS; it++) {
            int slot = tid + it * 256;
            if (slot < BK * BCH) {
                int r = slot / BCH, ch = slot % BCH;
                cpa16(smem_u32(&Bs[boff + r * BP + ch * 8]),
                      Bg + (size_t)(k0 + r) * Nd + colBase + ch * 8, true);
            }
        }
        cp_commit();
    };

    const int T = K / BK;
    issue(0, 0);
    if (T > 1) issue(1, 1);

    for (int t = 0; t < T; t++) {
        if (t + 2 < T) {
            issue(t + 2, (t + 2) % NSTG);
            cp_wait2();
        } else if (t + 1 < T) {
            cp_wait1();
        } else {
            cp_wait0();
        }
        __syncthreads();

        int stage = t % NSTG;
        unsigned aoff = stage * ASTG;
        unsigned boff = stage * BSTG;
#pragma unroll
        for (int ks = 0; ks < 2; ks++) {
            const int kk = ks * 16;
            unsigned bf[NT][2];
#pragma unroll
            for (int p = 0; p < NT / 2; p++) {
                int k = kk + (lane & 15);
                int n = wn * (BN / WN) + p * 16 + (lane >> 4) * 8;
                unsigned tb[4];
                ldsm_x4_t(tb, smem_u32(&Bs[boff + k * BP + n]));
                bf[2 * p][0] = tb[0]; bf[2 * p][1] = tb[1];
                bf[2 * p + 1][0] = tb[2]; bf[2 * p + 1][1] = tb[3];
            }
#pragma unroll
            for (int mt = 0; mt < MT; mt++) {
                unsigned a[4];
                int r = wm * (BM / WM) + mt * 16 + (lane & 15);
                int c = kk + (lane >> 4) * 8;
                ldsm_x4(a, smem_u32(&As[aoff + r * AP + c]));
#pragma unroll
                for (int nt = 0; nt < NT; nt++)
                    mma_f16(acc[mt][nt], a, bf[nt]);
            }
        }
        __syncthreads();
    }

#pragma unroll
    for (int mt = 0; mt < MT; mt++) {
        int r0 = rowBase + wm * (BM / WM) + mt * 16 + g;
#pragma unroll
        for (int nt = 0; nt < NT; nt++) {
            int cn = colBase + wn * (BN / WN) + nt * 8 + t4 * 2;
            if (r0 < M)
                *(__half2*)&C[(size_t)r0 * Nd + cn] =
                    __floats2half2_rn(acc[mt][nt][0], acc[mt][nt][1]);
            if (r0 + 8 < M)
                *(__half2*)&C[(size_t)(r0 + 8) * Nd + cn] =
                    __floats2half2_rn(acc[mt][nt][2], acc[mt][nt][3]);
        }
    }
}

__global__ __launch_bounds__(256, 2) void k_gemm1() {
    gemm_f16<128, 2, 4>(g_x16, g_w116, g_H1, Nn, IN_DIM, HIDD);
}

__global__ __launch_bounds__(256, 2) void k_gemm2() {
    gemm_f16<64, 4, 2>(g_s116, g_w216, g_H2, Nn, HIDD, OUTD);
}

// ---------------- SpMM 1: S1 = relu(csr_spmm(H1)+b1) -> fp16, unroll 8 ----------------
__global__ __launch_bounds__(128) void k_spmm1(const float* __restrict__ b1) {
    int row = blockIdx.x;
    int d2 = threadIdx.x;            // half2 column 0..127
    const __half2* H = (const __half2*)g_H1;
    int s = g_rowptr[row];
    int e = g_rowptr[row + 1];
    float ax = 0.0f, ay = 0.0f, bx = 0.0f, by = 0.0f;
    int j = s;
    for (; j + 8 <= e; j += 8) {
        uint2 ed[8];
#pragma unroll
        for (int q = 0; q < 8; q++) ed[q] = g_edge[j + q];
        float2 h[8];
#pragma unroll
        for (int q = 0; q < 8; q++) h[q] = __half22float2(H[(size_t)ed[q].x * 128 + d2]);
#pragma unroll
        for (int q = 0; q < 8; q += 2) {
            float v0 = __uint_as_float(ed[q].y);
            float v1 = __uint_as_float(ed[q + 1].y);
            ax = fmaf(v0, h[q].x, ax);     ay = fmaf(v0, h[q].y, ay);
            bx = fmaf(v1, h[q + 1].x, bx); by = fmaf(v1, h[q + 1].y, by);
        }
    }
    for (; j < e; j++) {
        uint2 ee = g_edge[j];
        float v = __uint_as_float(ee.y);
        float2 h = __half22float2(H[(size_t)ee.x * 128 + d2]);
        ax = fmaf(v, h.x, ax); ay = fmaf(v, h.y, ay);
    }
    ax += bx; ay += by;
    float2 bb = ((const float2*)b1)[d2];
    float ox = fmaxf(ax + bb.x, 0.0f);
    float oy = fmaxf(ay + bb.y, 0.0f);
    ((__half2*)g_s116)[(size_t)row * 128 + d2] = __floats2half2_rn(ox, oy);
}

// ---------------- SpMM 2: out = csr_spmm(H2) + b2, 8 rows/block ----------------
__global__ __launch_bounds__(256) void k_spmm2(const float* __restrict__ b2,
                                               float* __restrict__ out) {
    int row = blockIdx.x * 8 + (threadIdx.x >> 5);
    int d2 = threadIdx.x & 31;
    if (row >= Nn) return;
    const __half2* H = (const __half2*)g_H2;
    int s = g_rowptr[row];
    int e = g_rowptr[row + 1];
    float ax = 0.0f, ay = 0.0f;
    int j = s;
    for (; j + 4 <= e; j += 4) {
        uint2 e0 = g_edge[j + 0], e1 = g_edge[j + 1], e2 = g_edge[j + 2], e3 = g_edge[j + 3];
        float v0 = __uint_as_float(e0.y), v1 = __uint_as_float(e1.y);
        float v2 = __uint_as_float(e2.y), v3 = __uint_as_float(e3.y);
        float2 h0 = __half22float2(H[(size_t)e0.x * 32 + d2]);
        float2 h1 = __half22float2(H[(size_t)e1.x * 32 + d2]);
        float2 h2 = __half22float2(H[(size_t)e2.x * 32 + d2]);
        float2 h3 = __half22float2(H[(size_t)e3.x * 32 + d2]);
        ax = fmaf(v0, h0.x, ax); ay = fmaf(v0, h0.y, ay);
        ax = fmaf(v1, h1.x, ax); ay = fmaf(v1, h1.y, ay);
        ax = fmaf(v2, h2.x, ax); ay = fmaf(v2, h2.y, ay);
        ax = fmaf(v3, h3.x, ax); ay = fmaf(v3, h3.y, ay);
    }
    for (; j < e; j++) {
        uint2 ee = g_edge[j];
        float v = __uint_as_float(ee.y);
        float2 h = __half22float2(H[(size_t)ee.x * 32 + d2]);
        ax = fmaf(v, h.x, ax); ay = fmaf(v, h.y, ay);
    }
    float2 bb = ((const float2*)b2)[d2];
    ((float2*)out)[(size_t)row * 32 + d2] = make_float2(ax + bb.x, ay + bb.y);
}

// ---------------- entry point ----------------
extern "C" void kernel_launch(void* const* d_in, const int* in_sizes, int n_in,
                              void* d_out, int out_size) {
    const float* x    = (const float*)d_in[0];
    const int*   rows = (const int*)  d_in[1];
    const int*   cols = (const int*)  d_in[2];
    const float* vals = (const float*)d_in[3];
    const float* W1   = (const float*)d_in[4];
    const float* b1   = (const float*)d_in[5];
    const float* W2   = (const float*)d_in[6];
    const float* b2   = (const float*)d_in[7];
    float* out = (float*)d_out;

    const int smem1 = (3 * 128 * 40 + 3 * 32 * (128 + 8)) * 2;  // 56832
    const int smem2 = (3 * 128 * 40 + 3 * 32 * (64 + 8)) * 2;   // 44544
    cudaFuncSetAttribute(k_gemm1, cudaFuncAttributeMaxDynamicSharedMemorySize, smem1);
    cudaFuncSetAttribute(k_gemm2, cudaFuncAttributeMaxDynamicSharedMemorySize, smem2);

    __half *x16, *w116, *w216;
    cudaGetSymbolAddress((void**)&x16,  g_x16);
    cudaGetSymbolAddress((void**)&w116, g_w116);
    cudaGetSymbolAddress((void**)&w216, g_w216);
    int* cnt;
    cudaGetSymbolAddress((void**)&cnt, g_cnt);

    // forked side stream for the CSR build (overlaps gemm1)
    cudaStream_t s2;
    cudaStreamCreateWithFlags(&s2, cudaStreamNonBlocking);
    cudaEvent_t eFork, eJoin;
    cudaEventCreateWithFlags(&eFork, cudaEventDisableTiming);
    cudaEventCreateWithFlags(&eJoin, cudaEventDisableTiming);

    // conversions; gemm1 stays the 4th kernel launch (ncu window)
    k_cvt16<<<(Nn * IN_DIM / 8 + 255) / 256, 256>>>(x, x16, Nn * IN_DIM / 8);
    k_cvt16<<<(IN_DIM * HIDD / 8 + 255) / 256, 256>>>(W1, w116, IN_DIM * HIDD / 8);
    k_cvt16<<<(HIDD * OUTD / 8 + 255) / 256, 256>>>(W2, w216, HIDD * OUTD / 8);

    // fork CSR build onto s2 (independent of the cvts/gemm1)
    cudaEventRecord(eFork, 0);
    cudaStreamWaitEvent(s2, eFork, 0);

    // layer 1 GEMM on the capture stream (4th kernel launch overall)
    k_gemm1<<<dim3((Nn + 127) / 128, HIDD / 128), 256, smem1>>>();

    // CSR build on s2, concurrent with gemm1
    cudaMemsetAsync(cnt, 0, Nn * sizeof(int), s2);
    k_hist<<<(Ee + 255) / 256, 256, 0, s2>>>(rows);
    k_scan1<<<(Nn + 511) / 512, 512, 0, s2>>>();
    k_scan2<<<1, 128, 0, s2>>>();
    k_scan3<<<(Nn + 511) / 512, 512, 0, s2>>>();
    k_scatter<<<(Ee + 255) / 256, 256, 0, s2>>>(rows, cols, vals);
    cudaEventRecord(eJoin, s2);

    // join: spmm1 needs gemm1 (stream 0) AND scatter (s2)
    cudaStreamWaitEvent(0, eJoin, 0);
    k_spmm1<<<Nn, 128>>>(b1);

    // layer 2
    k_gemm2<<<dim3((Nn + 127) / 128, 1), 256, smem2>>>();
    k_spmm2<<<(Nn + 7) / 8, 256>>>(b2, out);
}

// round 11
// speedup vs baseline: 4.3708x; 1.2193x over previous
#include <cuda_runtime.h>
#include <cuda_fp16.h>

#define Nn      50000
#define Ee      800000
#define IN_DIM  512
#define HIDD    256
#define OUTD    64

typedef unsigned short u16;
typedef unsigned int   u32;

// ---------------- scratch (device globals; no allocs allowed) ----------------
__device__ __half    g_H1[(size_t)Nn * HIDD];        // x @ W1 (fp16)
__device__ __half    g_H2[(size_t)Nn * OUTD];        // S1 @ W2 (fp16)
__device__ __half    g_x16[(size_t)Nn * IN_DIM];     // x as fp16
__device__ __half    g_s116[(size_t)Nn * HIDD];      // S1 as fp16
__device__ __half    g_w116[IN_DIM * HIDD];          // W1 fp16 [K][N]
__device__ __half    g_w216[HIDD * OUTD];            // W2 fp16
__device__ int       g_cnt[Nn];
__device__ int       g_rowptr[Nn + 1];
__device__ int       g_blksum[128];
__device__ uint2     g_edge[Ee];                      // (col, val bits)

// ---------------- helpers ----------------
__device__ __forceinline__ u32 smem_u32(const void* p) {
    return (u32)__cvta_generic_to_shared(p);
}

__device__ __forceinline__ void cpa16(u32 dst, const void* src, bool pred) {
    int sz = pred ? 16 : 0;
    asm volatile("cp.async.cg.shared.global [%0], [%1], 16, %2;\n"
                 :: "r"(dst), "l"(src), "r"(sz));
}
__device__ __forceinline__ void cp_commit() { asm volatile("cp.async.commit_group;\n"); }
__device__ __forceinline__ void cp_wait2()  { asm volatile("cp.async.wait_group 2;\n"); }
__device__ __forceinline__ void cp_wait1()  { asm volatile("cp.async.wait_group 1;\n"); }
__device__ __forceinline__ void cp_wait0()  { asm volatile("cp.async.wait_group 0;\n"); }

__device__ __forceinline__ void ldsm_x4(unsigned* r, unsigned addr) {
    asm volatile("ldmatrix.sync.aligned.m8n8.x4.shared.b16 {%0,%1,%2,%3}, [%4];"
                 : "=r"(r[0]), "=r"(r[1]), "=r"(r[2]), "=r"(r[3]) : "r"(addr));
}

__device__ __forceinline__ void ldsm_x4_t(unsigned* r, unsigned addr) {
    asm volatile("ldmatrix.sync.aligned.m8n8.x4.trans.shared.b16 {%0,%1,%2,%3}, [%4];"
                 : "=r"(r[0]), "=r"(r[1]), "=r"(r[2]), "=r"(r[3]) : "r"(addr));
}

__device__ __forceinline__ void mma_f16(float* d, const unsigned* a, const unsigned* b) {
    asm volatile(
        "mma.sync.aligned.m16n8k16.row.col.f32.f16.f16.f32 "
        "{%0,%1,%2,%3}, {%4,%5,%6,%7}, {%8,%9}, {%0,%1,%2,%3};\n"
        : "+f"(d[0]), "+f"(d[1]), "+f"(d[2]), "+f"(d[3])
        : "r"(a[0]), "r"(a[1]), "r"(a[2]), "r"(a[3]), "r"(b[0]), "r"(b[1]));
}

// ---------------- conversions ----------------
__global__ void k_cvt16(const float* __restrict__ in, __half* __restrict__ outp, int n8) {
    int i = blockIdx.x * blockDim.x + threadIdx.x;
    if (i >= n8) return;
    float4 a = ((const float4*)in)[2 * i];
    float4 b = ((const float4*)in)[2 * i + 1];
    __half2 h0 = __floats2half2_rn(a.x, a.y);
    __half2 h1 = __floats2half2_rn(a.z, a.w);
    __half2 h2 = __floats2half2_rn(b.x, b.y);
    __half2 h3 = __floats2half2_rn(b.z, b.w);
    uint4 v;
    v.x = *(u32*)&h0; v.y = *(u32*)&h1; v.z = *(u32*)&h2; v.w = *(u32*)&h3;
    ((uint4*)outp)[i] = v;
}

// ---------------- CSR build ----------------
__global__ void k_hist(const int* __restrict__ rows) {
    int e = blockIdx.x * blockDim.x + threadIdx.x;
    if (e < Ee) atomicAdd(&g_cnt[rows[e]], 1);
}

__global__ __launch_bounds__(512) void k_scan1() {
    __shared__ int sm[512];
    int b = blockIdx.x, t = threadIdx.x;
    int i = b * 512 + t;
    int v = (i < Nn) ? g_cnt[i] : 0;
    sm[t] = v;
    __syncthreads();
    for (int off = 1; off < 512; off <<= 1) {
        int add = (t >= off) ? sm[t - off] : 0;
        __syncthreads();
        sm[t] += add;
        __syncthreads();
    }
    if (i < Nn) g_rowptr[i] = sm[t] - v;
    if (t == 511) g_blksum[b] = sm[511];
}

__global__ __launch_bounds__(128) void k_scan2() {
    const int NB = (Nn + 511) / 512;  // 98
    __shared__ int sm[128];
    int t = threadIdx.x;
    int v = (t < NB) ? g_blksum[t] : 0;
    sm[t] = v;
    __syncthreads();
    for (int off = 1; off < 128; off <<= 1) {
        int add = (t >= off) ? sm[t - off] : 0;
        __syncthreads();
        sm[t] += add;
        __syncthreads();
    }
    if (t < NB) g_blksum[t] = sm[t] - v;
}

__global__ __launch_bounds__(512) void k_scan3() {
    int b = blockIdx.x;
    int i = b * 512 + threadIdx.x;
    if (i < Nn) {
        g_rowptr[i] += g_blksum[b];
        g_cnt[i] = 0;
    }
    if (i == 0) g_rowptr[Nn] = Ee;
}

__global__ void k_scatter(const int* __restrict__ rows,
                          const int* __restrict__ cols,
                          const float* __restrict__ vals) {
    int e = blockIdx.x * blockDim.x + threadIdx.x;
    if (e >= Ee) return;
    int r = rows[e];
    int pos = g_rowptr[r] + atomicAdd(&g_cnt[r], 1);
    g_edge[pos] = make_uint2((u32)cols[e], __float_as_uint(vals[e]));
}

// ---------------- 3-stage pipelined fp16 tensor GEMM, fp16 output ----------------
template <int BN, int WM, int WN>
__device__ __forceinline__ void gemm_f16(const __half* __restrict__ Ag,
                                         const __half* __restrict__ Bg,
                                         __half* __restrict__ C,
                                         int M, int K, int Nd) {
    constexpr int BM = 128, BK = 32;
    constexpr int AP = 40;           // A smem row stride: 80B, odd 16B units
    constexpr int BP = BN + 8;       // B smem row stride (odd 16B units)
    constexpr int MT = (BM / WM) / 16;
    constexpr int NT = (BN / WN) / 8;
    constexpr int NSTG = 3;
    constexpr int ASTG = BM * AP;
    constexpr int BSTG = BK * BP;

    extern __shared__ u16 sm[];
    u16* As = sm;
    u16* Bs = As + NSTG * ASTG;

    const int tid = threadIdx.x;
    const int lane = tid & 31;
    const int warp = tid >> 5;
    const int wm = warp / WN;
    const int wn = warp % WN;
    const int g = lane >> 2;
    const int t4 = lane & 3;
    const int rowBase = blockIdx.x * BM;
    const int colBase = blockIdx.y * BN;

    float acc[MT][NT][4];
#pragma unroll
    for (int mt = 0; mt < MT; mt++)
#pragma unroll
        for (int nt = 0; nt < NT; nt++)
#pragma unroll
            for (int i = 0; i < 4; i++) acc[mt][nt][i] = 0.0f;

    constexpr int ACH = BK / 8;
    constexpr int A_ITERS = BM * ACH / 256;   // 2
    constexpr int BCH = BN / 8;
    constexpr int B_ITERS = (BK * BCH + 255) / 256;

    auto issue = [&](int t, int stage) {
        int k0 = t * BK;
        unsigned aoff = stage * ASTG;
        unsigned boff = stage * BSTG;
#pragma unroll
        for (int it = 0; it < A_ITERS; it++) {
            int slot = tid + it * 256;
            int r = slot >> 2, ch = slot & 3;
            int gr = rowBase + r;
            bool p = gr < M;
            cpa16(smem_u32(&As[aoff + r * AP + ch * 8]),
                  Ag + (size_t)gr * K + k0 + ch * 8, p);
        }
#pragma unroll
        for (int it = 0; it < B_ITERS; it++) {
            int slot = tid + it * 256;
            if (slot < BK * BCH) {
                int r = slot / BCH, ch = slot % BCH;
                cpa16(smem_u32(&Bs[boff + r * BP + ch * 8]),
                      Bg + (size_t)(k0 + r) * Nd + colBase + ch * 8, true);
            }
        }
        cp_commit();
    };

    const int T = K / BK;
    issue(0, 0);
    if (T > 1) issue(1, 1);

    for (int t = 0; t < T; t++) {
        if (t + 2 < T) {
            issue(t + 2, (t + 2) % NSTG);
            cp_wait2();
        } else if (t + 1 < T) {
            cp_wait1();
        } else {
            cp_wait0();
        }
        __syncthreads();

        int stage = t % NSTG;
        unsigned aoff = stage * ASTG;
        unsigned boff = stage * BSTG;
#pragma unroll
        for (int ks = 0; ks < 2; ks++) {
            const int kk = ks * 16;
            unsigned bf[NT][2];
#pragma unroll
            for (int p = 0; p < NT / 2; p++) {
                int k = kk + (lane & 15);
                int n = wn * (BN / WN) + p * 16 + (lane >> 4) * 8;
                unsigned tb[4];
                ldsm_x4_t(tb, smem_u32(&Bs[boff + k * BP + n]));
                bf[2 * p][0] = tb[0]; bf[2 * p][1] = tb[1];
                bf[2 * p + 1][0] = tb[2]; bf[2 * p + 1][1] = tb[3];
            }
#pragma unroll
            for (int mt = 0; mt < MT; mt++) {
                unsigned a[4];
                int r = wm * (BM / WM) + mt * 16 + (lane & 15);
                int c = kk + (lane >> 4) * 8;
                ldsm_x4(a, smem_u32(&As[aoff + r * AP + c]));
#pragma unroll
                for (int nt = 0; nt < NT; nt++)
                    mma_f16(acc[mt][nt], a, bf[nt]);
            }
        }
        __syncthreads();
    }

#pragma unroll
    for (int mt = 0; mt < MT; mt++) {
        int r0 = rowBase + wm * (BM / WM) + mt * 16 + g;
#pragma unroll
        for (int nt = 0; nt < NT; nt++) {
            int cn = colBase + wn * (BN / WN) + nt * 8 + t4 * 2;
            if (r0 < M)
                *(__half2*)&C[(size_t)r0 * Nd + cn] =
                    __floats2half2_rn(acc[mt][nt][0], acc[mt][nt][1]);
            if (r0 + 8 < M)
                *(__half2*)&C[(size_t)(r0 + 8) * Nd + cn] =
                    __floats2half2_rn(acc[mt][nt][2], acc[mt][nt][3]);
        }
    }
}

__global__ __launch_bounds__(256, 2) void k_gemm1() {
    gemm_f16<128, 2, 4>(g_x16, g_w116, g_H1, Nn, IN_DIM, HIDD);
}

__global__ __launch_bounds__(256, 2) void k_gemm2() {
    gemm_f16<64, 4, 2>(g_s116, g_w216, g_H2, Nn, HIDD, OUTD);
}

// ---------------- SpMM 1: 32 threads/row, float4 (8-dim) gathers ----------------
__global__ __launch_bounds__(256) void k_spmm1(const float* __restrict__ b1) {
    int row = blockIdx.x * 8 + (threadIdx.x >> 5);
    int lane = threadIdx.x & 31;           // dims [lane*8, lane*8+8)
    if (row >= Nn) return;
    const float4* H4 = (const float4*)g_H1;   // 32 float4 per row
    int s = g_rowptr[row];
    int e = g_rowptr[row + 1];
    float acc[8] = {0, 0, 0, 0, 0, 0, 0, 0};
    int j = s;
    for (; j + 4 <= e; j += 4) {
        uint2 ed[4];
#pragma unroll
        for (int q = 0; q < 4; q++) ed[q] = g_edge[j + q];
        float4 hv[4];
#pragma unroll
        for (int q = 0; q < 4; q++) hv[q] = H4[(size_t)ed[q].x * 32 + lane];
#pragma unroll
        for (int q = 0; q < 4; q++) {
            float v = __uint_as_float(ed[q].y);
            const __half2* hp = (const __half2*)&hv[q];
#pragma unroll
            for (int w = 0; w < 4; w++) {
                float2 f = __half22float2(hp[w]);
                acc[2 * w]     = fmaf(v, f.x, acc[2 * w]);
                acc[2 * w + 1] = fmaf(v, f.y, acc[2 * w + 1]);
            }
        }
    }
    for (; j < e; j++) {
        uint2 ee = g_edge[j];
        float v = __uint_as_float(ee.y);
        float4 hv = H4[(size_t)ee.x * 32 + lane];
        const __half2* hp = (const __half2*)&hv;
#pragma unroll
        for (int w = 0; w < 4; w++) {
            float2 f = __half22float2(hp[w]);
            acc[2 * w]     = fmaf(v, f.x, acc[2 * w]);
            acc[2 * w + 1] = fmaf(v, f.y, acc[2 * w + 1]);
        }
    }
    // bias + relu + fp16 store (16B)
    float4 bb0 = ((const float4*)b1)[2 * lane];
    float4 bb1 = ((const float4*)b1)[2 * lane + 1];
    float bv[8] = {bb0.x, bb0.y, bb0.z, bb0.w, bb1.x, bb1.y, bb1.z, bb1.w};
    __half2 o[4];
#pragma unroll
    for (int w = 0; w < 4; w++)
        o[w] = __floats2half2_rn(fmaxf(acc[2 * w] + bv[2 * w], 0.0f),
                                 fmaxf(acc[2 * w + 1] + bv[2 * w + 1], 0.0f));
    uint4 pk;
    pk.x = *(u32*)&o[0]; pk.y = *(u32*)&o[1]; pk.z = *(u32*)&o[2]; pk.w = *(u32*)&o[3];
    ((uint4*)g_s116)[(size_t)row * 32 + lane] = pk;
}

// ---------------- SpMM 2: out = csr_spmm(H2) + b2, 8 rows/block ----------------
__global__ __launch_bounds__(256) void k_spmm2(const float* __restrict__ b2,
                                               float* __restrict__ out) {
    int row = blockIdx.x * 8 + (threadIdx.x >> 5);
    int d2 = threadIdx.x & 31;
    if (row >= Nn) return;
    const __half2* H = (const __half2*)g_H2;
    int s = g_rowptr[row];
    int e = g_rowptr[row + 1];
    float ax = 0.0f, ay = 0.0f;
    int j = s;
    for (; j + 4 <= e; j += 4) {
        uint2 e0 = g_edge[j + 0], e1 = g_edge[j + 1], e2 = g_edge[j + 2], e3 = g_edge[j + 3];
        float v0 = __uint_as_float(e0.y), v1 = __uint_as_float(e1.y);
        float v2 = __uint_as_float(e2.y), v3 = __uint_as_float(e3.y);
        float2 h0 = __half22float2(H[(size_t)e0.x * 32 + d2]);
        float2 h1 = __half22float2(H[(size_t)e1.x * 32 + d2]);
        float2 h2 = __half22float2(H[(size_t)e2.x * 32 + d2]);
        float2 h3 = __half22float2(H[(size_t)e3.x * 32 + d2]);
        ax = fmaf(v0, h0.x, ax); ay = fmaf(v0, h0.y, ay);
        ax = fmaf(v1, h1.x, ax); ay = fmaf(v1, h1.y, ay);
        ax = fmaf(v2, h2.x, ax); ay = fmaf(v2, h2.y, ay);
        ax = fmaf(v3, h3.x, ax); ay = fmaf(v3, h3.y, ay);
    }
    for (; j < e; j++) {
        uint2 ee = g_edge[j];
        float v = __uint_as_float(ee.y);
        float2 h = __half22float2(H[(size_t)ee.x * 32 + d2]);
        ax = fmaf(v, h.x, ax); ay = fmaf(v, h.y, ay);
    }
    float2 bb = ((const float2*)b2)[d2];
    ((float2*)out)[(size_t)row * 32 + d2] = make_float2(ax + bb.x, ay + bb.y);
}

// ---------------- entry point ----------------
extern "C" void kernel_launch(void* const* d_in, const int* in_sizes, int n_in,
                              void* d_out, int out_size) {
    const float* x    = (const float*)d_in[0];
    const int*   rows = (const int*)  d_in[1];
    const int*   cols = (const int*)  d_in[2];
    const float* vals = (const float*)d_in[3];
    const float* W1   = (const float*)d_in[4];
    const float* b1   = (const float*)d_in[5];
    const float* W2   = (const float*)d_in[6];
    const float* b2   = (const float*)d_in[7];
    float* out = (float*)d_out;

    const int smem1 = (3 * 128 * 40 + 3 * 32 * (128 + 8)) * 2;  // 56832
    const int smem2 = (3 * 128 * 40 + 3 * 32 * (64 + 8)) * 2;   // 44544
    cudaFuncSetAttribute(k_gemm1, cudaFuncAttributeMaxDynamicSharedMemorySize, smem1);
    cudaFuncSetAttribute(k_gemm2, cudaFuncAttributeMaxDynamicSharedMemorySize, smem2);

    __half *x16, *w116, *w216;
    cudaGetSymbolAddress((void**)&x16,  g_x16);
    cudaGetSymbolAddress((void**)&w116, g_w116);
    cudaGetSymbolAddress((void**)&w216, g_w216);
    int* cnt;
    cudaGetSymbolAddress((void**)&cnt, g_cnt);

    cudaStream_t s2;
    cudaStreamCreateWithFlags(&s2, cudaStreamNonBlocking);
    cudaEvent_t eFork, eJoin;
    cudaEventCreateWithFlags(&eFork, cudaEventDisableTiming);
    cudaEventCreateWithFlags(&eJoin, cudaEventDisableTiming);

    // conversions; gemm1 stays the 4th kernel launch (ncu window)
    k_cvt16<<<(Nn * IN_DIM / 8 + 255) / 256, 256>>>(x, x16, Nn * IN_DIM / 8);
    k_cvt16<<<(IN_DIM * HIDD / 8 + 255) / 256, 256>>>(W1, w116, IN_DIM * HIDD / 8);
    k_cvt16<<<(HIDD * OUTD / 8 + 255) / 256, 256>>>(W2, w216, HIDD * OUTD / 8);

    // fork CSR build onto s2 (independent of the cvts/gemm1)
    cudaEventRecord(eFork, 0);
    cudaStreamWaitEvent(s2, eFork, 0);

    // layer 1 GEMM on the capture stream
    k_gemm1<<<dim3((Nn + 127) / 128, HIDD / 128), 256, smem1>>>();

    // CSR build on s2, concurrent with gemm1
    cudaMemsetAsync(cnt, 0, Nn * sizeof(int), s2);
    k_hist<<<(Ee + 255) / 256, 256, 0, s2>>>(rows);
    k_scan1<<<(Nn + 511) / 512, 512, 0, s2>>>();
    k_scan2<<<1, 128, 0, s2>>>();
    k_scan3<<<(Nn + 511) / 512, 512, 0, s2>>>();
    k_scatter<<<(Ee + 255) / 256, 256, 0, s2>>>(rows, cols, vals);
    cudaEventRecord(eJoin, s2);

    // join: spmm1 needs gemm1 (stream 0) AND scatter (s2)
    cudaStreamWaitEvent(0, eJoin, 0);
    k_spmm1<<<(Nn + 7) / 8, 256>>>(b1);

    // layer 2
    k_gemm2<<<dim3((Nn + 127) / 128, 1), 256, smem2>>>();
    k_spmm2<<<(Nn + 7) / 8, 256>>>(b2, out);
}